// round 2
// baseline (speedup 1.0000x reference)
#include <cuda_runtime.h>
#include <math.h>
#include <stdint.h>

// Problem constants
#define GG 32          // B*S graphs
#define NA 64          // atoms per graph
#define HH 300         // hidden
#define AF 133         // atom feature dim
#define BF 147         // bond feature dim
#define AR (GG*NA)     // 2048 atom rows
#define BR (GG*NA*NA)  // 131072 bond rows

// Scratch (static device globals: allocation-free per harness rules)
__device__ float g_input_atom[AR*HH];
__device__ float g_msg_atom[AR*HH];
__device__ float g_agg[AR*HH];
__device__ float g_maW[AR*HH];
__device__ float g_input_bond[BR*HH];   // 157 MB
__device__ float g_mbA[BR*HH];          // 157 MB
__device__ float g_mbB[BR*HH];          // 157 MB (fallback mb_final)
__device__ float g_C[BR*HH];            // 157 MB (prev @ W scratch)
__device__ float g_sm[BR];              // softmax(resonance)

// ---------------------------------------------------------------------------
// Packed f32x2 helpers (Blackwell FFMA2)
// ---------------------------------------------------------------------------
__device__ __forceinline__ unsigned long long pack2(float x, float y) {
    unsigned long long r;
    asm("mov.b64 %0, {%1, %2};" : "=l"(r)
        : "r"(__float_as_uint(x)), "r"(__float_as_uint(y)));
    return r;
}
__device__ __forceinline__ void ffma2(unsigned long long& d, unsigned long long a,
                                      unsigned long long b) {
    asm("fma.rn.f32x2 %0, %1, %2, %3;" : "=l"(d) : "l"(a), "l"(b), "l"(d));
}
__device__ __forceinline__ float2 unpack2(unsigned long long v) {
    unsigned lo, hi;
    asm("mov.b64 {%0, %1}, %2;" : "=r"(lo), "=r"(hi) : "l"(v));
    return make_float2(__uint_as_float(lo), __uint_as_float(hi));
}

// ---------------------------------------------------------------------------
// Generic f32x2 SGEMM: C[M,N] = op(A[M,K] (optionally row-scaled) @ W[K,N])
// BM=128, BN=64, BK=12, 128 threads, 8x8 microtile.
// M must be a multiple of 128. N = 300 here (guards on cols).
// ---------------------------------------------------------------------------
#define BKg 12
template<int SCALED, int RELU>
__global__ void k_gemm_f2(const float* __restrict__ A, const float* __restrict__ W,
                          float* __restrict__ C, int K, int N,
                          const float* __restrict__ rowScale) {
    const int row0 = blockIdx.y * 128;
    const int col0 = blockIdx.x * 64;
    __shared__ __align__(16) float As[BKg][136];
    __shared__ __align__(16) float Bs[BKg][72];
    __shared__ float scs[128];
    const int tid = threadIdx.x;          // 128 threads
    const int rg = tid >> 3;              // 0..15 row group (8 rows)
    const int cg = tid & 7;               // 0..7  col group (8 cols)
    if (SCALED) scs[tid] = rowScale[row0 + tid];

    unsigned long long acc[8][4];
    #pragma unroll
    for (int i = 0; i < 8; i++)
        #pragma unroll
        for (int p = 0; p < 4; p++) acc[i][p] = 0ull;

    const int nIter = (K + BKg - 1) / BKg;
    for (int it = 0; it < nIter; ++it) {
        const int k0 = it * BKg;
        __syncthreads();
        // A fill: 128 rows x 12 k
        #pragma unroll
        for (int l = tid; l < 128 * BKg; l += 128) {
            int r = l / BKg, k = l - r * BKg;
            int gk = k0 + k;
            float v = (gk < K) ? A[(size_t)(row0 + r) * K + gk] : 0.f;
            if (SCALED) v *= scs[r];
            As[k][r] = v;
        }
        // B fill: 12 k x 64 cols
        #pragma unroll
        for (int l = tid; l < 64 * BKg; l += 128) {
            int k = l >> 6, c = l & 63;
            int gk = k0 + k, gc = col0 + c;
            Bs[k][c] = (gk < K && gc < N) ? W[(size_t)gk * N + gc] : 0.f;
        }
        __syncthreads();
        #pragma unroll
        for (int kk = 0; kk < BKg; ++kk) {
            float4 a0 = *(const float4*)&As[kk][rg * 8];
            float4 a1 = *(const float4*)&As[kk][rg * 8 + 4];
            ulonglong2 b01 = *(const ulonglong2*)&Bs[kk][cg * 8];
            ulonglong2 b23 = *(const ulonglong2*)&Bs[kk][cg * 8 + 4];
            float av[8] = {a0.x, a0.y, a0.z, a0.w, a1.x, a1.y, a1.z, a1.w};
            #pragma unroll
            for (int i = 0; i < 8; i++) {
                unsigned long long ap = pack2(av[i], av[i]);
                ffma2(acc[i][0], ap, b01.x);
                ffma2(acc[i][1], ap, b01.y);
                ffma2(acc[i][2], ap, b23.x);
                ffma2(acc[i][3], ap, b23.y);
            }
        }
    }
    const bool fastcol = (col0 + 64 <= N);
    #pragma unroll
    for (int i = 0; i < 8; i++) {
        size_t row = row0 + rg * 8 + i;
        float v[8];
        #pragma unroll
        for (int p = 0; p < 4; p++) {
            float2 f = unpack2(acc[i][p]);
            v[2 * p] = f.x; v[2 * p + 1] = f.y;
        }
        if (RELU) {
            #pragma unroll
            for (int jj = 0; jj < 8; jj++) v[jj] = fmaxf(v[jj], 0.f);
        }
        size_t base = row * N + col0 + cg * 8;
        if (fastcol) {
            *(float4*)&C[base]     = make_float4(v[0], v[1], v[2], v[3]);
            *(float4*)&C[base + 4] = make_float4(v[4], v[5], v[6], v[7]);
        } else {
            #pragma unroll
            for (int jj = 0; jj < 8; jj++)
                if (col0 + cg * 8 + jj < N) C[base + jj] = v[jj];
        }
    }
}

// ---------------------------------------------------------------------------
// GEMM: input_atom = relu(f_atoms @ W_i_atom); also copies to msg_atom.
// ---------------------------------------------------------------------------
__global__ void k_input_atom(const float* __restrict__ A, const float* __restrict__ W) {
    const int row0 = blockIdx.y * 64;
    const int col0 = blockIdx.x * 64;
    __shared__ float As[16][68];
    __shared__ float Bs[16][68];
    const int tid = threadIdx.x;
    const int tx = tid & 15, ty = tid >> 4;
    float acc[4][4] = {};
    for (int k0 = 0; k0 < AF; k0 += 16) {
        __syncthreads();
        {
            int kk = tid & 15;
            int k  = k0 + kk;
            #pragma unroll
            for (int q = 0; q < 4; q++) {
                int r = (tid >> 4) + q * 16;
                As[kk][r] = (k < AF) ? A[(row0 + r) * AF + k] : 0.f;
            }
        }
        {
            int nn = tid & 63;
            int c  = col0 + nn;
            #pragma unroll
            for (int q = 0; q < 4; q++) {
                int kk = (tid >> 6) + q * 4;
                int k  = k0 + kk;
                Bs[kk][nn] = (k < AF && c < HH) ? W[k * HH + c] : 0.f;
            }
        }
        __syncthreads();
        #pragma unroll
        for (int kk = 0; kk < 16; kk++) {
            float4 a4 = *(const float4*)&As[kk][ty * 4];
            float4 b4 = *(const float4*)&Bs[kk][tx * 4];
            float a[4] = {a4.x, a4.y, a4.z, a4.w};
            float b[4] = {b4.x, b4.y, b4.z, b4.w};
            #pragma unroll
            for (int i = 0; i < 4; i++)
                #pragma unroll
                for (int j = 0; j < 4; j++)
                    acc[i][j] += a[i] * b[j];
        }
    }
    #pragma unroll
    for (int i = 0; i < 4; i++) {
        int r = row0 + ty * 4 + i;
        #pragma unroll
        for (int j = 0; j < 4; j++) {
            int c = col0 + tx * 4 + j;
            if (c < HH) {
                float v = acc[i][j];
                v = v > 0.f ? v : 0.f;
                g_input_atom[r * HH + c] = v;
                g_msg_atom[r * HH + c]   = v;
            }
        }
    }
}

// ---------------------------------------------------------------------------
// Standalone agg (used once, on input_bond):
// agg[g,m,h] = sum_n mb[g,n,m,h] * sigmoid(max_n mb[g,n,m,h]); msg_atom += agg
// ---------------------------------------------------------------------------
__global__ void k_agg(const float* __restrict__ mb) {
    int gm = blockIdx.x;
    int h = threadIdx.x;
    if (h >= HH) return;
    int g = gm >> 6, m = gm & 63;
    const float* base = mb + ((size_t)(g * 64) * 64 + m) * HH + h;
    float s = 0.f, mx = -INFINITY;
    #pragma unroll 4
    for (int n = 0; n < 64; n++) {
        float v = base[(size_t)n * 64 * HH];
        s += v;
        mx = fmaxf(mx, v);
    }
    float a = s * (1.f / (1.f + expf(-mx)));
    g_msg_atom[gm * HH + h] += a;
}

// ---------------------------------------------------------------------------
// Resonance + softmax, one block per graph. Gram matrix via smem tiles.
// g_sm[(g*64+n)*64+m] = softmax_n( dot(ma[g,n],ma[g,m]) * adj[g,n,m] )
// ---------------------------------------------------------------------------
__global__ void k_resonance2(const float* __restrict__ adj) {
    int g = blockIdx.x;
    __shared__ float mt[64][101];
    __shared__ float rr[64][65];
    int tid = threadIdx.x;        // 256
    int tx = tid & 15, ty = tid >> 4;
    float acc[4][4] = {};
    for (int c = 0; c < 3; ++c) {
        __syncthreads();
        for (int l = tid; l < 6400; l += 256) {
            int r = l / 100, k = l - r * 100;
            mt[r][k] = g_msg_atom[((size_t)(g * 64 + r)) * 300 + c * 100 + k];
        }
        __syncthreads();
        for (int kk = 0; kk < 100; ++kk) {
            float a[4], b[4];
            #pragma unroll
            for (int i = 0; i < 4; i++) a[i] = mt[ty * 4 + i][kk];
            #pragma unroll
            for (int j = 0; j < 4; j++) b[j] = mt[tx * 4 + j][kk];
            #pragma unroll
            for (int i = 0; i < 4; i++)
                #pragma unroll
                for (int j = 0; j < 4; j++)
                    acc[i][j] += a[i] * b[j];
        }
    }
    #pragma unroll
    for (int i = 0; i < 4; i++)
        #pragma unroll
        for (int j = 0; j < 4; j++)
            rr[ty * 4 + i][tx * 4 + j] = acc[i][j];
    __syncthreads();
    if (tid < 64) {
        int m = tid;
        float mxv = -INFINITY;
        for (int n = 0; n < 64; n++) {
            float v = rr[n][m] * adj[((size_t)(g * 64 + n)) * 64 + m];
            rr[n][m] = v;
            mxv = fmaxf(mxv, v);
        }
        float sum = 0.f;
        for (int n = 0; n < 64; n++) {
            float e = expf(rr[n][m] - mxv);
            rr[n][m] = e;
            sum += e;
        }
        float inv = 1.f / sum;
        for (int n = 0; n < 64; n++)
            g_sm[(size_t)(g * 64 + n) * 64 + m] = rr[n][m] * inv;
    }
}

// ---------------------------------------------------------------------------
// Fused epilogue + agg:
// mb[g,i,j,:] = relu(ib[g,i,j,:] + adj[g,j,i]*maW[g,i,:] - C[g,j,i,:]) * sm[i,j]
// then agg[g,j,h] = sum_i mb * sigmoid(max_i mb); msg_atom += agg (or -> g_agg)
// Block = (g, j). 128 threads over h (h, h+128, h+256).
// ---------------------------------------------------------------------------
__global__ void k_epilogue(const float* __restrict__ ib, const float* __restrict__ maW,
                           const float* __restrict__ Cm, const float* __restrict__ adj,
                           float* __restrict__ mb, int update) {
    int gj = blockIdx.x;
    int g = gj >> 6, j = gj & 63;
    __shared__ float adjT[64], smv[64];
    int tid = threadIdx.x;        // 128
    if (tid < 64) {
        adjT[tid] = adj[((size_t)(g * 64 + j)) * 64 + tid];     // adj[g,j,i]
        smv[tid]  = g_sm[((size_t)(g * 64 + tid)) * 64 + j];    // sm[n=i, m=j]
    }
    __syncthreads();
    int nh = (tid + 256 < 300) ? 3 : 2;
    int hs[3] = {tid, tid + 128, tid + 256};
    float s[3] = {0.f, 0.f, 0.f};
    float mx[3] = {-INFINITY, -INFINITY, -INFINITY};
    for (int i = 0; i < 64; ++i) {
        size_t rowOut = ((size_t)(g * 64 + i) * 64 + j) * 300;
        size_t rowC   = ((size_t)(g * 64 + j) * 64 + i) * 300;
        size_t rowM   = (size_t)(g * 64 + i) * 300;
        float a = adjT[i], w = smv[i];
        #pragma unroll
        for (int q = 0; q < 3; q++) {
            if (q < nh) {
                int h = hs[q];
                float v = ib[rowOut + h] + a * maW[rowM + h] - Cm[rowC + h];
                v = fmaxf(v, 0.f) * w;
                mb[rowOut + h] = v;
                s[q] += v;
                mx[q] = fmaxf(mx[q], v);
            }
        }
    }
    #pragma unroll
    for (int q = 0; q < 3; q++) {
        if (q < nh) {
            float aggv = s[q] * (1.f / (1.f + expf(-mx[q])));
            size_t idx = (size_t)(g * 64 + j) * 300 + hs[q];
            if (update) g_msg_atom[idx] += aggv;
            else        g_agg[idx] = aggv;
        }
    }
}

// ---------------------------------------------------------------------------
// Output GEMM: atom_hiddens = relu([agg, msg_atom, input_atom] @ W_o + b_o)
// ---------------------------------------------------------------------------
__global__ void k_output(const float* __restrict__ W, const float* __restrict__ bias,
                         float* __restrict__ out) {
    const int row0 = blockIdx.y * 64;
    const int col0 = blockIdx.x * 64;
    __shared__ float As[16][68];
    __shared__ float Bs[16][68];
    const int tid = threadIdx.x;
    const int tx = tid & 15, ty = tid >> 4;
    float acc[4][4] = {};
    for (int k0 = 0; k0 < 900; k0 += 16) {
        __syncthreads();
        {
            int kk = tid & 15;
            int k  = k0 + kk;
            #pragma unroll
            for (int q = 0; q < 4; q++) {
                int r = (tid >> 4) + q * 16;
                int row = row0 + r;
                float v = 0.f;
                if (k < 900) {
                    if (k < 300)       v = g_agg[row * HH + k];
                    else if (k < 600)  v = g_msg_atom[row * HH + (k - 300)];
                    else               v = g_input_atom[row * HH + (k - 600)];
                }
                As[kk][r] = v;
            }
        }
        {
            int nn = tid & 63;
            int c  = col0 + nn;
            #pragma unroll
            for (int q = 0; q < 4; q++) {
                int kk = (tid >> 6) + q * 4;
                int k  = k0 + kk;
                Bs[kk][nn] = (k < 900 && c < HH) ? W[k * HH + c] : 0.f;
            }
        }
        __syncthreads();
        #pragma unroll
        for (int kk = 0; kk < 16; kk++) {
            float4 a4 = *(const float4*)&As[kk][ty * 4];
            float4 b4 = *(const float4*)&Bs[kk][tx * 4];
            float a[4] = {a4.x, a4.y, a4.z, a4.w};
            float b[4] = {b4.x, b4.y, b4.z, b4.w};
            #pragma unroll
            for (int i = 0; i < 4; i++)
                #pragma unroll
                for (int j = 0; j < 4; j++)
                    acc[i][j] += a[i] * b[j];
        }
    }
    #pragma unroll
    for (int i = 0; i < 4; i++) {
        int r = row0 + ty * 4 + i;
        #pragma unroll
        for (int j = 0; j < 4; j++) {
            int c = col0 + tx * 4 + j;
            if (c < HH) {
                float v = acc[i][j] + bias[c];
                out[r * HH + c] = v > 0.f ? v : 0.f;
            }
        }
    }
}

// ---------------------------------------------------------------------------
extern "C" void kernel_launch(void* const* d_in, const int* in_sizes, int n_in,
                              void* d_out, int out_size) {
    const float* f_atoms  = (const float*)d_in[0];
    const float* f_bonds  = (const float*)d_in[1];
    const float* adj      = (const float*)d_in[2];
    const float* W_i_atom = (const float*)d_in[3];
    const float* W_i_bond = (const float*)d_in[4];
    const float* W_h0     = (const float*)d_in[5];
    const float* W_h1     = (const float*)d_in[6];
    const float* W_o      = (const float*)d_in[7];
    const float* b_o      = (const float*)d_in[8];
    float* out = (float*)d_out;

    float *p_inbond = 0, *p_mbA = 0, *p_mbB = 0, *p_C = 0, *p_msg = 0, *p_maW = 0;
    cudaGetSymbolAddress((void**)&p_inbond, g_input_bond);
    cudaGetSymbolAddress((void**)&p_mbA, g_mbA);
    cudaGetSymbolAddress((void**)&p_mbB, g_mbB);
    cudaGetSymbolAddress((void**)&p_C, g_C);
    cudaGetSymbolAddress((void**)&p_msg, g_msg_atom);
    cudaGetSymbolAddress((void**)&p_maW, g_maW);

    // Output layout: [atom_hiddens (2048*300) | message_bond (131072*300)].
    float* mb_final = (out_size >= AR * HH + BR * HH) ? (out + AR * HH) : p_mbB;

    k_input_atom<<<dim3(5, 32), 256>>>(f_atoms, W_i_atom);
    // input_bond = relu((adj ⊙ f_bonds) @ W_i_bond)
    k_gemm_f2<1, 1><<<dim3(5, 1024), 128>>>(f_bonds, W_i_bond, p_inbond, BF, HH, adj);

    // ---- depth step 0 (prev = input_bond) ----
    k_agg<<<2048, 320>>>(p_inbond);                    // msg_atom += agg(mb0)
    k_resonance2<<<32, 256>>>(adj);                    // -> g_sm
    k_gemm_f2<0, 0><<<dim3(5, 16), 128>>>(p_msg, W_h0, p_maW, HH, HH, nullptr);
    k_gemm_f2<0, 0><<<dim3(5, 1024), 128>>>(p_inbond, W_h0, p_C, HH, HH, nullptr);
    k_epilogue<<<2048, 128>>>(p_inbond, p_maW, p_C, adj, p_mbA, 1); // mb1 + msg_atom update

    // ---- depth step 1 (prev = mbA) ----
    k_resonance2<<<32, 256>>>(adj);
    k_gemm_f2<0, 0><<<dim3(5, 16), 128>>>(p_msg, W_h1, p_maW, HH, HH, nullptr);
    k_gemm_f2<0, 0><<<dim3(5, 1024), 128>>>(p_mbA, W_h1, p_C, HH, HH, nullptr);
    k_epilogue<<<2048, 128>>>(p_inbond, p_maW, p_C, adj, mb_final, 0); // mb2 + g_agg

    // ---- readout ----
    k_output<<<dim3(5, 32), 256>>>(W_o, b_o, out);
}

// round 4
// speedup vs baseline: 2.0506x; 2.0506x over previous
#include <cuda_runtime.h>
#include <math.h>
#include <stdint.h>

// Problem constants
#define GG 32          // B*S graphs
#define NA 64          // atoms per graph
#define HH 300         // hidden
#define AF 133         // atom feature dim
#define BF 147         // bond feature dim
#define AR (GG*NA)     // 2048 atom rows
#define BR (GG*NA*NA)  // 131072 bond rows

// Scratch (static device globals: allocation-free per harness rules)
__device__ float g_input_atom[AR*HH];
__device__ float g_msg_atom[AR*HH];
__device__ float g_agg[AR*HH];
__device__ float g_maW[AR*HH];
__device__ float g_input_bond[BR*HH];   // 157 MB
__device__ float g_mbA[BR*HH];          // 157 MB
__device__ float g_mbB[BR*HH];          // 157 MB (fallback mb_final)
__device__ float g_C[BR*HH];            // 157 MB (prev @ W scratch)
__device__ float g_sm[BR];              // softmax(resonance)

// ---------------------------------------------------------------------------
// Packed f32x2 helpers (Blackwell FFMA2)
// ---------------------------------------------------------------------------
__device__ __forceinline__ unsigned long long pack2(float x, float y) {
    unsigned long long r;
    asm("mov.b64 %0, {%1, %2};" : "=l"(r)
        : "r"(__float_as_uint(x)), "r"(__float_as_uint(y)));
    return r;
}
__device__ __forceinline__ void ffma2(unsigned long long& d, unsigned long long a,
                                      unsigned long long b) {
    asm("fma.rn.f32x2 %0, %1, %2, %3;" : "=l"(d) : "l"(a), "l"(b), "l"(d));
}
__device__ __forceinline__ float2 unpack2(unsigned long long v) {
    unsigned lo, hi;
    asm("mov.b64 {%0, %1}, %2;" : "=r"(lo), "=r"(hi) : "l"(v));
    return make_float2(__uint_as_float(lo), __uint_as_float(hi));
}

// ---------------------------------------------------------------------------
// f32x2 SGEMM: C[M,N] = op(A[M,K] (opt row-scaled) @ W[K,N])
// BM=128, BN=64, BK=12, 128 threads, 8x8 microtile, register prefetch.
// A loads use float4 only when K%4==0 (alignment!); otherwise scalar loads.
// ---------------------------------------------------------------------------
#define BKg 12
template<int K, int SCALED, int RELU>
__global__ __launch_bounds__(128, 3)
void k_gemm_f2(const float* __restrict__ A, const float* __restrict__ W,
               float* __restrict__ Co, int N, const float* __restrict__ rowScale) {
    constexpr bool A_VEC = (K % 4 == 0);
    const int row0 = blockIdx.y * 128;
    const int col0 = blockIdx.x * 64;
    __shared__ __align__(16) float As[BKg][132];   // [k][row]
    __shared__ __align__(16) float Bs[BKg][72];    // [k][col]
    const int tid = threadIdx.x;
    const int rg = tid >> 3;        // 0..15 (8 rows each)
    const int cg = tid & 7;         // 0..7  (8 cols each)

    // --- fixed fill geometry: 128 rows x 3 quads of 4 k-values ---
    int ar[3], ac4[3];
    #pragma unroll
    for (int q = 0; q < 3; q++) {
        int l = q * 128 + tid;
        ar[q]  = l / 3;
        ac4[q] = l - ar[q] * 3;
    }
    float asc[3];
    #pragma unroll
    for (int q = 0; q < 3; q++)
        asc[q] = SCALED ? rowScale[row0 + ar[q]] : 1.f;

    const int bk0  = tid >> 4;            // k row 0..7
    const int bk1  = (tid + 128) >> 4;    // k row 8..11 (tid<64)
    const int bc4  = tid & 15;
    const bool hasB1  = (tid < 64);
    const bool bcolOK = (col0 + 4 * bc4 + 4 <= N);

    unsigned long long acc[8][4];
    #pragma unroll
    for (int i = 0; i < 8; i++)
        #pragma unroll
        for (int p = 0; p < 4; p++) acc[i][p] = 0ull;

    float4 ra[3], rb0, rb1;

    auto load_tile = [&](int k0) {
        #pragma unroll
        for (int q = 0; q < 3; q++) {
            int gk = k0 + 4 * ac4[q];
            const float* ap = &A[(size_t)(row0 + ar[q]) * K + gk];
            if (A_VEC && gk + 4 <= K) {
                ra[q] = *(const float4*)ap;
            } else {
                float v[4];
                #pragma unroll
                for (int e = 0; e < 4; e++) v[e] = (gk + e < K) ? ap[e] : 0.f;
                ra[q] = make_float4(v[0], v[1], v[2], v[3]);
            }
        }
        // W is [K, 300]: N=300 -> any row base is 16B-aligned, col offset mult of 4.
        {
            int gk = k0 + bk0;
            if (gk < K && bcolOK)
                rb0 = *(const float4*)&W[(size_t)gk * N + col0 + 4 * bc4];
            else rb0 = make_float4(0.f, 0.f, 0.f, 0.f);
        }
        if (hasB1) {
            int gk = k0 + bk1;
            if (gk < K && bcolOK)
                rb1 = *(const float4*)&W[(size_t)gk * N + col0 + 4 * bc4];
            else rb1 = make_float4(0.f, 0.f, 0.f, 0.f);
        }
    };

    const int nIter = (K + BKg - 1) / BKg;
    load_tile(0);
    int k0 = 0;
    for (int it = 0; it < nIter; ++it) {
        __syncthreads();
        #pragma unroll
        for (int q = 0; q < 3; q++) {
            int kb = 4 * ac4[q];
            float s = asc[q];
            As[kb + 0][ar[q]] = ra[q].x * s;
            As[kb + 1][ar[q]] = ra[q].y * s;
            As[kb + 2][ar[q]] = ra[q].z * s;
            As[kb + 3][ar[q]] = ra[q].w * s;
        }
        *(float4*)&Bs[bk0][4 * bc4] = rb0;
        if (hasB1) *(float4*)&Bs[bk1][4 * bc4] = rb1;
        __syncthreads();
        if (it + 1 < nIter) load_tile(k0 + BKg);
        #pragma unroll
        for (int kk = 0; kk < BKg; ++kk) {
            float4 a0 = *(const float4*)&As[kk][rg * 8];
            float4 a1 = *(const float4*)&As[kk][rg * 8 + 4];
            ulonglong2 b01 = *(const ulonglong2*)&Bs[kk][cg * 8];
            ulonglong2 b23 = *(const ulonglong2*)&Bs[kk][cg * 8 + 4];
            float av[8] = {a0.x, a0.y, a0.z, a0.w, a1.x, a1.y, a1.z, a1.w};
            #pragma unroll
            for (int i = 0; i < 8; i++) {
                unsigned long long ap = pack2(av[i], av[i]);
                ffma2(acc[i][0], ap, b01.x);
                ffma2(acc[i][1], ap, b01.y);
                ffma2(acc[i][2], ap, b23.x);
                ffma2(acc[i][3], ap, b23.y);
            }
        }
        k0 += BKg;
    }

    const bool fastcol = (col0 + 64 <= N);
    #pragma unroll
    for (int i = 0; i < 8; i++) {
        size_t row = row0 + rg * 8 + i;
        float v[8];
        #pragma unroll
        for (int p = 0; p < 4; p++) {
            float2 f = unpack2(acc[i][p]);
            v[2 * p] = f.x; v[2 * p + 1] = f.y;
        }
        if (RELU) {
            #pragma unroll
            for (int jj = 0; jj < 8; jj++) v[jj] = fmaxf(v[jj], 0.f);
        }
        size_t base = row * N + col0 + cg * 8;
        if (fastcol) {
            *(float4*)&Co[base]     = make_float4(v[0], v[1], v[2], v[3]);
            *(float4*)&Co[base + 4] = make_float4(v[4], v[5], v[6], v[7]);
        } else {
            #pragma unroll
            for (int jj = 0; jj < 8; jj++)
                if (col0 + cg * 8 + jj < N) Co[base + jj] = v[jj];
        }
    }
}

// ---------------------------------------------------------------------------
// GEMM: input_atom = relu(f_atoms @ W_i_atom); also copies to msg_atom.
// ---------------------------------------------------------------------------
__global__ void k_input_atom(const float* __restrict__ A, const float* __restrict__ W) {
    const int row0 = blockIdx.y * 64;
    const int col0 = blockIdx.x * 64;
    __shared__ float As[16][68];
    __shared__ float Bs[16][68];
    const int tid = threadIdx.x;
    const int tx = tid & 15, ty = tid >> 4;
    float acc[4][4] = {};
    for (int k0 = 0; k0 < AF; k0 += 16) {
        __syncthreads();
        {
            int kk = tid & 15;
            int k  = k0 + kk;
            #pragma unroll
            for (int q = 0; q < 4; q++) {
                int r = (tid >> 4) + q * 16;
                As[kk][r] = (k < AF) ? A[(row0 + r) * AF + k] : 0.f;
            }
        }
        {
            int nn = tid & 63;
            int c  = col0 + nn;
            #pragma unroll
            for (int q = 0; q < 4; q++) {
                int kk = (tid >> 6) + q * 4;
                int k  = k0 + kk;
                Bs[kk][nn] = (k < AF && c < HH) ? W[k * HH + c] : 0.f;
            }
        }
        __syncthreads();
        #pragma unroll
        for (int kk = 0; kk < 16; kk++) {
            float4 a4 = *(const float4*)&As[kk][ty * 4];
            float4 b4 = *(const float4*)&Bs[kk][tx * 4];
            float a[4] = {a4.x, a4.y, a4.z, a4.w};
            float b[4] = {b4.x, b4.y, b4.z, b4.w};
            #pragma unroll
            for (int i = 0; i < 4; i++)
                #pragma unroll
                for (int j = 0; j < 4; j++)
                    acc[i][j] += a[i] * b[j];
        }
    }
    #pragma unroll
    for (int i = 0; i < 4; i++) {
        int r = row0 + ty * 4 + i;
        #pragma unroll
        for (int j = 0; j < 4; j++) {
            int c = col0 + tx * 4 + j;
            if (c < HH) {
                float v = acc[i][j];
                v = v > 0.f ? v : 0.f;
                g_input_atom[r * HH + c] = v;
                g_msg_atom[r * HH + c]   = v;
            }
        }
    }
}

// ---------------------------------------------------------------------------
// Standalone agg (used once, on input_bond):
// agg[g,m,h] = sum_n mb[g,n,m,h] * sigmoid(max_n mb[g,n,m,h]); msg_atom += agg
// ---------------------------------------------------------------------------
__global__ void k_agg(const float* __restrict__ mb) {
    int gm = blockIdx.x;
    int h = threadIdx.x;
    if (h >= HH) return;
    int g = gm >> 6, m = gm & 63;
    const float* base = mb + ((size_t)(g * 64) * 64 + m) * HH + h;
    float s = 0.f, mx = -INFINITY;
    #pragma unroll 4
    for (int n = 0; n < 64; n++) {
        float v = base[(size_t)n * 64 * HH];
        s += v;
        mx = fmaxf(mx, v);
    }
    float a = s * (1.f / (1.f + expf(-mx)));
    g_msg_atom[gm * HH + h] += a;
}

// ---------------------------------------------------------------------------
// Resonance + softmax, one block per graph. Gram matrix via smem tiles.
// ---------------------------------------------------------------------------
__global__ void k_resonance2(const float* __restrict__ adj) {
    int g = blockIdx.x;
    __shared__ float mt[64][101];
    __shared__ float rr[64][65];
    int tid = threadIdx.x;        // 256
    int tx = tid & 15, ty = tid >> 4;
    float acc[4][4] = {};
    for (int c = 0; c < 3; ++c) {
        __syncthreads();
        for (int l = tid; l < 6400; l += 256) {
            int r = l / 100, k = l - r * 100;
            mt[r][k] = g_msg_atom[((size_t)(g * 64 + r)) * 300 + c * 100 + k];
        }
        __syncthreads();
        for (int kk = 0; kk < 100; ++kk) {
            float a[4], b[4];
            #pragma unroll
            for (int i = 0; i < 4; i++) a[i] = mt[ty * 4 + i][kk];
            #pragma unroll
            for (int j = 0; j < 4; j++) b[j] = mt[tx * 4 + j][kk];
            #pragma unroll
            for (int i = 0; i < 4; i++)
                #pragma unroll
                for (int j = 0; j < 4; j++)
                    acc[i][j] += a[i] * b[j];
        }
    }
    #pragma unroll
    for (int i = 0; i < 4; i++)
        #pragma unroll
        for (int j = 0; j < 4; j++)
            rr[ty * 4 + i][tx * 4 + j] = acc[i][j];
    __syncthreads();
    if (tid < 64) {
        int m = tid;
        float mxv = -INFINITY;
        for (int n = 0; n < 64; n++) {
            float v = rr[n][m] * adj[((size_t)(g * 64 + n)) * 64 + m];
            rr[n][m] = v;
            mxv = fmaxf(mxv, v);
        }
        float sum = 0.f;
        for (int n = 0; n < 64; n++) {
            float e = expf(rr[n][m] - mxv);
            rr[n][m] = e;
            sum += e;
        }
        float inv = 1.f / sum;
        for (int n = 0; n < 64; n++)
            g_sm[(size_t)(g * 64 + n) * 64 + m] = rr[n][m] * inv;
    }
}

// ---------------------------------------------------------------------------
// Fused epilogue + agg:
// mb[g,i,j,:] = relu(ib[g,i,j,:] + adj[g,j,i]*maW[g,i,:] - C[g,j,i,:]) * sm[i,j]
// then agg over i; msg_atom += agg (update=1) or -> g_agg (update=0)
// ---------------------------------------------------------------------------
__global__ void k_epilogue(const float* __restrict__ ib, const float* __restrict__ maW,
                           const float* __restrict__ Cm, const float* __restrict__ adj,
                           float* __restrict__ mb, int update) {
    int gj = blockIdx.x;
    int g = gj >> 6, j = gj & 63;
    __shared__ float adjT[64], smv[64];
    int tid = threadIdx.x;        // 128
    if (tid < 64) {
        adjT[tid] = adj[((size_t)(g * 64 + j)) * 64 + tid];     // adj[g,j,i]
        smv[tid]  = g_sm[((size_t)(g * 64 + tid)) * 64 + j];    // sm[n=i, m=j]
    }
    __syncthreads();
    int nh = (tid + 256 < 300) ? 3 : 2;
    int hs[3] = {tid, tid + 128, tid + 256};
    float s[3] = {0.f, 0.f, 0.f};
    float mx[3] = {-INFINITY, -INFINITY, -INFINITY};
    for (int i = 0; i < 64; ++i) {
        size_t rowOut = ((size_t)(g * 64 + i) * 64 + j) * 300;
        size_t rowC   = ((size_t)(g * 64 + j) * 64 + i) * 300;
        size_t rowM   = (size_t)(g * 64 + i) * 300;
        float a = adjT[i], w = smv[i];
        #pragma unroll
        for (int q = 0; q < 3; q++) {
            if (q < nh) {
                int h = hs[q];
                float v = ib[rowOut + h] + a * maW[rowM + h] - Cm[rowC + h];
                v = fmaxf(v, 0.f) * w;
                mb[rowOut + h] = v;
                s[q] += v;
                mx[q] = fmaxf(mx[q], v);
            }
        }
    }
    #pragma unroll
    for (int q = 0; q < 3; q++) {
        if (q < nh) {
            float aggv = s[q] * (1.f / (1.f + expf(-mx[q])));
            size_t idx = (size_t)(g * 64 + j) * 300 + hs[q];
            if (update) g_msg_atom[idx] += aggv;
            else        g_agg[idx] = aggv;
        }
    }
}

// ---------------------------------------------------------------------------
// Output GEMM: atom_hiddens = relu([agg, msg_atom, input_atom] @ W_o + b_o)
// ---------------------------------------------------------------------------
__global__ void k_output(const float* __restrict__ W, const float* __restrict__ bias,
                         float* __restrict__ out) {
    const int row0 = blockIdx.y * 64;
    const int col0 = blockIdx.x * 64;
    __shared__ float As[16][68];
    __shared__ float Bs[16][68];
    const int tid = threadIdx.x;
    const int tx = tid & 15, ty = tid >> 4;
    float acc[4][4] = {};
    for (int k0 = 0; k0 < 900; k0 += 16) {
        __syncthreads();
        {
            int kk = tid & 15;
            int k  = k0 + kk;
            #pragma unroll
            for (int q = 0; q < 4; q++) {
                int r = (tid >> 4) + q * 16;
                int row = row0 + r;
                float v = 0.f;
                if (k < 900) {
                    if (k < 300)       v = g_agg[row * HH + k];
                    else if (k < 600)  v = g_msg_atom[row * HH + (k - 300)];
                    else               v = g_input_atom[row * HH + (k - 600)];
                }
                As[kk][r] = v;
            }
        }
        {
            int nn = tid & 63;
            int c  = col0 + nn;
            #pragma unroll
            for (int q = 0; q < 4; q++) {
                int kk = (tid >> 6) + q * 4;
                int k  = k0 + kk;
                Bs[kk][nn] = (k < 900 && c < HH) ? W[k * HH + c] : 0.f;
            }
        }
        __syncthreads();
        #pragma unroll
        for (int kk = 0; kk < 16; kk++) {
            float4 a4 = *(const float4*)&As[kk][ty * 4];
            float4 b4 = *(const float4*)&Bs[kk][tx * 4];
            float a[4] = {a4.x, a4.y, a4.z, a4.w};
            float b[4] = {b4.x, b4.y, b4.z, b4.w};
            #pragma unroll
            for (int i = 0; i < 4; i++)
                #pragma unroll
                for (int j = 0; j < 4; j++)
                    acc[i][j] += a[i] * b[j];
        }
    }
    #pragma unroll
    for (int i = 0; i < 4; i++) {
        int r = row0 + ty * 4 + i;
        #pragma unroll
        for (int j = 0; j < 4; j++) {
            int c = col0 + tx * 4 + j;
            if (c < HH) {
                float v = acc[i][j] + bias[c];
                out[r * HH + c] = v > 0.f ? v : 0.f;
            }
        }
    }
}

// ---------------------------------------------------------------------------
extern "C" void kernel_launch(void* const* d_in, const int* in_sizes, int n_in,
                              void* d_out, int out_size) {
    const float* f_atoms  = (const float*)d_in[0];
    const float* f_bonds  = (const float*)d_in[1];
    const float* adj      = (const float*)d_in[2];
    const float* W_i_atom = (const float*)d_in[3];
    const float* W_i_bond = (const float*)d_in[4];
    const float* W_h0     = (const float*)d_in[5];
    const float* W_h1     = (const float*)d_in[6];
    const float* W_o      = (const float*)d_in[7];
    const float* b_o      = (const float*)d_in[8];
    float* out = (float*)d_out;

    float *p_inbond = 0, *p_mbA = 0, *p_mbB = 0, *p_C = 0, *p_msg = 0, *p_maW = 0;
    cudaGetSymbolAddress((void**)&p_inbond, g_input_bond);
    cudaGetSymbolAddress((void**)&p_mbA, g_mbA);
    cudaGetSymbolAddress((void**)&p_mbB, g_mbB);
    cudaGetSymbolAddress((void**)&p_C, g_C);
    cudaGetSymbolAddress((void**)&p_msg, g_msg_atom);
    cudaGetSymbolAddress((void**)&p_maW, g_maW);

    // Output layout: [atom_hiddens (2048*300) | message_bond (131072*300)].
    float* mb_final = (out_size >= AR * HH + BR * HH) ? (out + AR * HH) : p_mbB;

    k_input_atom<<<dim3(5, 32), 256>>>(f_atoms, W_i_atom);
    // input_bond = relu((adj ⊙ f_bonds) @ W_i_bond)   (K=147 -> scalar A loads)
    k_gemm_f2<BF, 1, 1><<<dim3(5, BR / 128), 128>>>(f_bonds, W_i_bond, p_inbond, HH, adj);

    // ---- depth step 0 (prev = input_bond) ----
    k_agg<<<2048, 320>>>(p_inbond);                    // msg_atom += agg(mb0)
    k_resonance2<<<32, 256>>>(adj);                    // -> g_sm
    k_gemm_f2<HH, 0, 0><<<dim3(5, AR / 128), 128>>>(p_msg, W_h0, p_maW, HH, nullptr);
    k_gemm_f2<HH, 0, 0><<<dim3(5, BR / 128), 128>>>(p_inbond, W_h0, p_C, HH, nullptr);
    k_epilogue<<<2048, 128>>>(p_inbond, p_maW, p_C, adj, p_mbA, 1);

    // ---- depth step 1 (prev = mbA) ----
    k_resonance2<<<32, 256>>>(adj);
    k_gemm_f2<HH, 0, 0><<<dim3(5, AR / 128), 128>>>(p_msg, W_h1, p_maW, HH, nullptr);
    k_gemm_f2<HH, 0, 0><<<dim3(5, BR / 128), 128>>>(p_mbA, W_h1, p_C, HH, nullptr);
    k_epilogue<<<2048, 128>>>(p_inbond, p_maW, p_C, adj, mb_final, 0);

    // ---- readout ----
    k_output<<<dim3(5, 32), 256>>>(W_o, b_o, out);
}

// round 5
// speedup vs baseline: 2.0942x; 1.0212x over previous
#include <cuda_runtime.h>
#include <math.h>
#include <stdint.h>

// Problem constants
#define GG 32          // B*S graphs
#define NA 64          // atoms per graph
#define HH 300         // hidden
#define AF 133         // atom feature dim
#define BF 147         // bond feature dim
#define AR (GG*NA)     // 2048 atom rows
#define BR (GG*NA*NA)  // 131072 bond rows

// Scratch (static device globals: allocation-free per harness rules)
__device__ float g_input_atom[AR*HH];
__device__ float g_msg_atom[AR*HH];
__device__ float g_agg[AR*HH];
__device__ float g_maW[AR*HH];
__device__ float g_input_bond[BR*HH];   // 157 MB
__device__ float g_mbA[BR*HH];          // 157 MB
__device__ float g_mbB[BR*HH];          // 157 MB (fallback mb_final)
__device__ float g_sm[BR];              // softmax(resonance)

// ---------------------------------------------------------------------------
// Packed f32x2 helpers (Blackwell FFMA2)
// ---------------------------------------------------------------------------
__device__ __forceinline__ unsigned long long pack2(float x, float y) {
    unsigned long long r;
    asm("mov.b64 %0, {%1, %2};" : "=l"(r)
        : "r"(__float_as_uint(x)), "r"(__float_as_uint(y)));
    return r;
}
__device__ __forceinline__ void ffma2(unsigned long long& d, unsigned long long a,
                                      unsigned long long b) {
    asm("fma.rn.f32x2 %0, %1, %2, %3;" : "=l"(d) : "l"(a), "l"(b), "l"(d));
}
__device__ __forceinline__ float2 unpack2(unsigned long long v) {
    unsigned lo, hi;
    asm("mov.b64 {%0, %1}, %2;" : "=r"(lo), "=r"(hi) : "l"(v));
    return make_float2(__uint_as_float(lo), __uint_as_float(hi));
}

// ---------------------------------------------------------------------------
// f32x2 SGEMM: C[M,N] = op(A[M,K] (opt row-scaled) @ W[K,N])
// BM=128, BN=64, BK=12, 128 threads, 8x8 microtile, register prefetch.
// Used for: input_bond (K=147, scalar A loads) and maW (K=300).
// ---------------------------------------------------------------------------
#define BKg 12
template<int K, int SCALED, int RELU>
__global__ __launch_bounds__(128, 3)
void k_gemm_f2(const float* __restrict__ A, const float* __restrict__ W,
               float* __restrict__ Co, int N, const float* __restrict__ rowScale) {
    constexpr bool A_VEC = (K % 4 == 0);
    const int row0 = blockIdx.y * 128;
    const int col0 = blockIdx.x * 64;
    __shared__ __align__(16) float As[BKg][132];   // [k][row]
    __shared__ __align__(16) float Bs[BKg][72];    // [k][col]
    const int tid = threadIdx.x;
    const int rg = tid >> 3;        // 0..15 (8 rows each)
    const int cg = tid & 7;         // 0..7  (8 cols each)

    int ar[3], ac4[3];
    #pragma unroll
    for (int q = 0; q < 3; q++) {
        int l = q * 128 + tid;
        ar[q]  = l / 3;
        ac4[q] = l - ar[q] * 3;
    }
    float asc[3];
    #pragma unroll
    for (int q = 0; q < 3; q++)
        asc[q] = SCALED ? rowScale[row0 + ar[q]] : 1.f;

    const int bk0  = tid >> 4;
    const int bk1  = (tid + 128) >> 4;
    const int bc4  = tid & 15;
    const bool hasB1  = (tid < 64);
    const bool bcolOK = (col0 + 4 * bc4 + 4 <= N);

    unsigned long long acc[8][4];
    #pragma unroll
    for (int i = 0; i < 8; i++)
        #pragma unroll
        for (int p = 0; p < 4; p++) acc[i][p] = 0ull;

    float4 ra[3], rb0, rb1;

    auto load_tile = [&](int k0) {
        #pragma unroll
        for (int q = 0; q < 3; q++) {
            int gk = k0 + 4 * ac4[q];
            const float* ap = &A[(size_t)(row0 + ar[q]) * K + gk];
            if (A_VEC && gk + 4 <= K) {
                ra[q] = *(const float4*)ap;
            } else {
                float v[4];
                #pragma unroll
                for (int e = 0; e < 4; e++) v[e] = (gk + e < K) ? ap[e] : 0.f;
                ra[q] = make_float4(v[0], v[1], v[2], v[3]);
            }
        }
        {
            int gk = k0 + bk0;
            if (gk < K && bcolOK)
                rb0 = *(const float4*)&W[(size_t)gk * N + col0 + 4 * bc4];
            else rb0 = make_float4(0.f, 0.f, 0.f, 0.f);
        }
        if (hasB1) {
            int gk = k0 + bk1;
            if (gk < K && bcolOK)
                rb1 = *(const float4*)&W[(size_t)gk * N + col0 + 4 * bc4];
            else rb1 = make_float4(0.f, 0.f, 0.f, 0.f);
        }
    };

    const int nIter = (K + BKg - 1) / BKg;
    load_tile(0);
    int k0 = 0;
    for (int it = 0; it < nIter; ++it) {
        __syncthreads();
        #pragma unroll
        for (int q = 0; q < 3; q++) {
            int kb = 4 * ac4[q];
            float s = asc[q];
            As[kb + 0][ar[q]] = ra[q].x * s;
            As[kb + 1][ar[q]] = ra[q].y * s;
            As[kb + 2][ar[q]] = ra[q].z * s;
            As[kb + 3][ar[q]] = ra[q].w * s;
        }
        *(float4*)&Bs[bk0][4 * bc4] = rb0;
        if (hasB1) *(float4*)&Bs[bk1][4 * bc4] = rb1;
        __syncthreads();
        if (it + 1 < nIter) load_tile(k0 + BKg);
        #pragma unroll
        for (int kk = 0; kk < BKg; ++kk) {
            float4 a0 = *(const float4*)&As[kk][rg * 8];
            float4 a1 = *(const float4*)&As[kk][rg * 8 + 4];
            ulonglong2 b01 = *(const ulonglong2*)&Bs[kk][cg * 8];
            ulonglong2 b23 = *(const ulonglong2*)&Bs[kk][cg * 8 + 4];
            float av[8] = {a0.x, a0.y, a0.z, a0.w, a1.x, a1.y, a1.z, a1.w};
            #pragma unroll
            for (int i = 0; i < 8; i++) {
                unsigned long long ap = pack2(av[i], av[i]);
                ffma2(acc[i][0], ap, b01.x);
                ffma2(acc[i][1], ap, b01.y);
                ffma2(acc[i][2], ap, b23.x);
                ffma2(acc[i][3], ap, b23.y);
            }
        }
        k0 += BKg;
    }

    const bool fastcol = (col0 + 64 <= N);
    #pragma unroll
    for (int i = 0; i < 8; i++) {
        size_t row = row0 + rg * 8 + i;
        float v[8];
        #pragma unroll
        for (int p = 0; p < 4; p++) {
            float2 f = unpack2(acc[i][p]);
            v[2 * p] = f.x; v[2 * p + 1] = f.y;
        }
        if (RELU) {
            #pragma unroll
            for (int jj = 0; jj < 8; jj++) v[jj] = fmaxf(v[jj], 0.f);
        }
        size_t base = row * N + col0 + cg * 8;
        if (fastcol) {
            *(float4*)&Co[base]     = make_float4(v[0], v[1], v[2], v[3]);
            *(float4*)&Co[base + 4] = make_float4(v[4], v[5], v[6], v[7]);
        } else {
            #pragma unroll
            for (int jj = 0; jj < 8; jj++)
                if (col0 + cg * 8 + jj < N) Co[base + jj] = v[jj];
        }
    }
}

// ---------------------------------------------------------------------------
// FUSED bond step: for block rows r = g*4096 + x*64 + y (x=j, y=i):
//   acc = (prev @ W)[row r]                       (same mainloop as k_gemm_f2)
//   val = relu( ib[g,y,x,c] + adj[g,x,y]*maW[g,y,c] - acc ) * sm[(g,y),x]
//   mbout[g,y,x,c] = val           (transposed store)
//   agg[g,x,c] = sum_y val * sigmoid(max_y val)
//   msg_atom[g,x,c] += agg  (UPDATE=1)  or  g_agg[g,x,c] = agg (UPDATE=0)
// Row tile = 128 rows => fixed g, x in {x0, x0+1}, y = 0..63 (full reduction).
// ---------------------------------------------------------------------------
template<int UPDATE>
__global__ __launch_bounds__(128, 3)
void k_bondstep(const float* __restrict__ A, const float* __restrict__ W,
                const float* __restrict__ ib, const float* __restrict__ maW,
                const float* __restrict__ adj, float* __restrict__ mbout) {
    const int row0 = blockIdx.y * 128;
    const int col0 = blockIdx.x * 64;
    const int g  = row0 >> 12;
    const int x0 = (row0 >> 6) & 63;
    __shared__ __align__(16) float As[BKg][132];
    __shared__ __align__(16) float Bs[BKg][72];
    __shared__ __align__(16) float maWs[64][68];
    __shared__ float adjs[128];      // adj[g, x0+xl, y] at [xl*64+y]
    __shared__ float smvs[2][64];    // g_sm[(g*64+y)*64 + x0+xl]
    __shared__ float psum[16][64];
    __shared__ float pmax[16][64];
    const int tid = threadIdx.x;
    const int rg = tid >> 3;        // 0..15
    const int cg = tid & 7;         // 0..7

    // --- epilogue operand tiles (visibility covered by mainloop syncthreads) ---
    adjs[tid] = adj[(size_t)(g * 64 + x0) * 64 + tid];   // 128 contiguous
    {
        int xl = tid >> 6, y = tid & 63;
        smvs[xl][y] = g_sm[(size_t)(g * 64 + y) * 64 + x0 + xl];
    }
    for (int l = tid; l < 64 * 16; l += 128) {           // 64 rows x 64 cols via float4
        int y = l >> 4, c4 = (l & 15) * 4;
        int c = col0 + c4;
        float4 v;
        if (c + 4 <= HH) v = *(const float4*)&maW[(size_t)(g * 64 + y) * HH + c];
        else {
            float t[4];
            #pragma unroll
            for (int e = 0; e < 4; e++) t[e] = (c + e < HH) ? maW[(size_t)(g * 64 + y) * HH + c + e] : 0.f;
            v = make_float4(t[0], t[1], t[2], t[3]);
        }
        *(float4*)&maWs[y][c4] = v;
    }

    // --- GEMM mainloop (identical to k_gemm_f2, K=HH=300, vectorized) ---
    int ar[3], ac4[3];
    #pragma unroll
    for (int q = 0; q < 3; q++) {
        int l = q * 128 + tid;
        ar[q]  = l / 3;
        ac4[q] = l - ar[q] * 3;
    }
    const int bk0  = tid >> 4;
    const int bk1  = (tid + 128) >> 4;
    const int bc4  = tid & 15;
    const bool hasB1  = (tid < 64);
    const bool bcolOK = (col0 + 4 * bc4 + 4 <= HH);

    unsigned long long acc[8][4];
    #pragma unroll
    for (int i = 0; i < 8; i++)
        #pragma unroll
        for (int p = 0; p < 4; p++) acc[i][p] = 0ull;

    float4 ra[3], rb0, rb1;
    auto load_tile = [&](int k0) {
        #pragma unroll
        for (int q = 0; q < 3; q++)
            ra[q] = *(const float4*)&A[(size_t)(row0 + ar[q]) * HH + k0 + 4 * ac4[q]];
        {
            int gk = k0 + bk0;
            rb0 = bcolOK ? *(const float4*)&W[(size_t)gk * HH + col0 + 4 * bc4]
                         : make_float4(0.f, 0.f, 0.f, 0.f);
        }
        if (hasB1) {
            int gk = k0 + bk1;
            rb1 = bcolOK ? *(const float4*)&W[(size_t)gk * HH + col0 + 4 * bc4]
                         : make_float4(0.f, 0.f, 0.f, 0.f);
        }
    };

    const int nIter = HH / BKg;    // 25, exact
    load_tile(0);
    int k0 = 0;
    for (int it = 0; it < nIter; ++it) {
        __syncthreads();
        #pragma unroll
        for (int q = 0; q < 3; q++) {
            int kb = 4 * ac4[q];
            As[kb + 0][ar[q]] = ra[q].x;
            As[kb + 1][ar[q]] = ra[q].y;
            As[kb + 2][ar[q]] = ra[q].z;
            As[kb + 3][ar[q]] = ra[q].w;
        }
        *(float4*)&Bs[bk0][4 * bc4] = rb0;
        if (hasB1) *(float4*)&Bs[bk1][4 * bc4] = rb1;
        __syncthreads();
        if (it + 1 < nIter) load_tile(k0 + BKg);
        #pragma unroll
        for (int kk = 0; kk < BKg; ++kk) {
            float4 a0 = *(const float4*)&As[kk][rg * 8];
            float4 a1 = *(const float4*)&As[kk][rg * 8 + 4];
            ulonglong2 b01 = *(const ulonglong2*)&Bs[kk][cg * 8];
            ulonglong2 b23 = *(const ulonglong2*)&Bs[kk][cg * 8 + 4];
            float av[8] = {a0.x, a0.y, a0.z, a0.w, a1.x, a1.y, a1.z, a1.w};
            #pragma unroll
            for (int i = 0; i < 8; i++) {
                unsigned long long ap = pack2(av[i], av[i]);
                ffma2(acc[i][0], ap, b01.x);
                ffma2(acc[i][1], ap, b01.y);
                ffma2(acc[i][2], ap, b23.x);
                ffma2(acc[i][3], ap, b23.y);
            }
        }
        k0 += BKg;
    }

    // --- fused epilogue ---
    const bool fastcol = (col0 + 64 <= HH);
    const int x_l = rg >> 3;                 // 0 or 1
    const int x   = x0 + x_l;
    float tsum[8], tmax[8];
    #pragma unroll
    for (int jj = 0; jj < 8; jj++) { tsum[jj] = 0.f; tmax[jj] = -INFINITY; }

    #pragma unroll
    for (int q = 0; q < 8; q++) {
        int lr = rg * 8 + q;                 // local row
        int y  = lr & 63;
        float a = adjs[x_l * 64 + y];
        float w = smvs[x_l][y];
        size_t obase = ((size_t)(g * 64 + y) * 64 + x) * HH + col0 + cg * 8;
        float v[8];
        #pragma unroll
        for (int p = 0; p < 4; p++) {
            float2 f = unpack2(acc[q][p]);
            v[2 * p] = f.x; v[2 * p + 1] = f.y;
        }
        if (fastcol) {
            float4 i0 = *(const float4*)&ib[obase];
            float4 i1 = *(const float4*)&ib[obase + 4];
            float iv[8] = {i0.x, i0.y, i0.z, i0.w, i1.x, i1.y, i1.z, i1.w};
            float o[8];
            #pragma unroll
            for (int jj = 0; jj < 8; jj++) {
                float val = iv[jj] + a * maWs[y][cg * 8 + jj] - v[jj];
                val = fmaxf(val, 0.f) * w;
                o[jj] = val;
                tsum[jj] += val;
                tmax[jj] = fmaxf(tmax[jj], val);
            }
            *(float4*)&mbout[obase]     = make_float4(o[0], o[1], o[2], o[3]);
            *(float4*)&mbout[obase + 4] = make_float4(o[4], o[5], o[6], o[7]);
        } else {
            #pragma unroll
            for (int jj = 0; jj < 8; jj++) {
                bool ok = (col0 + cg * 8 + jj < HH);
                float iv = ok ? ib[obase + jj] : 0.f;
                float val = iv + a * maWs[y][cg * 8 + jj] - v[jj];
                val = fmaxf(val, 0.f) * w;
                if (ok) mbout[obase + jj] = val;
                tsum[jj] += val;
                tmax[jj] = fmaxf(tmax[jj], val);
            }
        }
    }
    #pragma unroll
    for (int jj = 0; jj < 8; jj++) {
        psum[rg][cg * 8 + jj] = tsum[jj];
        pmax[rg][cg * 8 + jj] = tmax[jj];
    }
    __syncthreads();
    {
        int xl = tid >> 6, c = tid & 63;
        if (col0 + c < HH) {
            float s = 0.f, m = -INFINITY;
            #pragma unroll
            for (int r = 0; r < 8; r++) {
                s += psum[xl * 8 + r][c];
                m = fmaxf(m, pmax[xl * 8 + r][c]);
            }
            float aggv = s * (1.f / (1.f + expf(-m)));
            size_t idx = (size_t)(g * 64 + x0 + xl) * HH + col0 + c;
            if (UPDATE) g_msg_atom[idx] += aggv;
            else        g_agg[idx] = aggv;
        }
    }
}

// ---------------------------------------------------------------------------
// GEMM: input_atom = relu(f_atoms @ W_i_atom); also copies to msg_atom.
// ---------------------------------------------------------------------------
__global__ void k_input_atom(const float* __restrict__ A, const float* __restrict__ W) {
    const int row0 = blockIdx.y * 64;
    const int col0 = blockIdx.x * 64;
    __shared__ float As[16][68];
    __shared__ float Bs[16][68];
    const int tid = threadIdx.x;
    const int tx = tid & 15, ty = tid >> 4;
    float acc[4][4] = {};
    for (int k0 = 0; k0 < AF; k0 += 16) {
        __syncthreads();
        {
            int kk = tid & 15;
            int k  = k0 + kk;
            #pragma unroll
            for (int q = 0; q < 4; q++) {
                int r = (tid >> 4) + q * 16;
                As[kk][r] = (k < AF) ? A[(row0 + r) * AF + k] : 0.f;
            }
        }
        {
            int nn = tid & 63;
            int c  = col0 + nn;
            #pragma unroll
            for (int q = 0; q < 4; q++) {
                int kk = (tid >> 6) + q * 4;
                int k  = k0 + kk;
                Bs[kk][nn] = (k < AF && c < HH) ? W[k * HH + c] : 0.f;
            }
        }
        __syncthreads();
        #pragma unroll
        for (int kk = 0; kk < 16; kk++) {
            float4 a4 = *(const float4*)&As[kk][ty * 4];
            float4 b4 = *(const float4*)&Bs[kk][tx * 4];
            float a[4] = {a4.x, a4.y, a4.z, a4.w};
            float b[4] = {b4.x, b4.y, b4.z, b4.w};
            #pragma unroll
            for (int i = 0; i < 4; i++)
                #pragma unroll
                for (int j = 0; j < 4; j++)
                    acc[i][j] += a[i] * b[j];
        }
    }
    #pragma unroll
    for (int i = 0; i < 4; i++) {
        int r = row0 + ty * 4 + i;
        #pragma unroll
        for (int j = 0; j < 4; j++) {
            int c = col0 + tx * 4 + j;
            if (c < HH) {
                float v = acc[i][j];
                v = v > 0.f ? v : 0.f;
                g_input_atom[r * HH + c] = v;
                g_msg_atom[r * HH + c]   = v;
            }
        }
    }
}

// ---------------------------------------------------------------------------
// Standalone agg (used once, on input_bond):
// agg[g,m,h] = sum_n mb[g,n,m,h] * sigmoid(max_n mb[g,n,m,h]); msg_atom += agg
// ---------------------------------------------------------------------------
__global__ void k_agg(const float* __restrict__ mb) {
    int gm = blockIdx.x;
    int h = threadIdx.x;
    if (h >= HH) return;
    int g = gm >> 6, m = gm & 63;
    const float* base = mb + ((size_t)(g * 64) * 64 + m) * HH + h;
    float s = 0.f, mx = -INFINITY;
    #pragma unroll 4
    for (int n = 0; n < 64; n++) {
        float v = base[(size_t)n * 64 * HH];
        s += v;
        mx = fmaxf(mx, v);
    }
    float a = s * (1.f / (1.f + expf(-mx)));
    g_msg_atom[gm * HH + h] += a;
}

// ---------------------------------------------------------------------------
// Resonance + softmax, one block per graph. Gram matrix via smem tiles.
// ---------------------------------------------------------------------------
__global__ void k_resonance2(const float* __restrict__ adj) {
    int g = blockIdx.x;
    __shared__ float mt[64][101];
    __shared__ float rr[64][65];
    int tid = threadIdx.x;        // 256
    int tx = tid & 15, ty = tid >> 4;
    float acc[4][4] = {};
    for (int c = 0; c < 3; ++c) {
        __syncthreads();
        for (int l = tid; l < 6400; l += 256) {
            int r = l / 100, k = l - r * 100;
            mt[r][k] = g_msg_atom[((size_t)(g * 64 + r)) * 300 + c * 100 + k];
        }
        __syncthreads();
        for (int kk = 0; kk < 100; ++kk) {
            float a[4], b[4];
            #pragma unroll
            for (int i = 0; i < 4; i++) a[i] = mt[ty * 4 + i][kk];
            #pragma unroll
            for (int j = 0; j < 4; j++) b[j] = mt[tx * 4 + j][kk];
            #pragma unroll
            for (int i = 0; i < 4; i++)
                #pragma unroll
                for (int j = 0; j < 4; j++)
                    acc[i][j] += a[i] * b[j];
        }
    }
    #pragma unroll
    for (int i = 0; i < 4; i++)
        #pragma unroll
        for (int j = 0; j < 4; j++)
            rr[ty * 4 + i][tx * 4 + j] = acc[i][j];
    __syncthreads();
    if (tid < 64) {
        int m = tid;
        float mxv = -INFINITY;
        for (int n = 0; n < 64; n++) {
            float v = rr[n][m] * adj[((size_t)(g * 64 + n)) * 64 + m];
            rr[n][m] = v;
            mxv = fmaxf(mxv, v);
        }
        float sum = 0.f;
        for (int n = 0; n < 64; n++) {
            float e = expf(rr[n][m] - mxv);
            rr[n][m] = e;
            sum += e;
        }
        float inv = 1.f / sum;
        for (int n = 0; n < 64; n++)
            g_sm[(size_t)(g * 64 + n) * 64 + m] = rr[n][m] * inv;
    }
}

// ---------------------------------------------------------------------------
// Output GEMM: atom_hiddens = relu([agg, msg_atom, input_atom] @ W_o + b_o)
// ---------------------------------------------------------------------------
__global__ void k_output(const float* __restrict__ W, const float* __restrict__ bias,
                         float* __restrict__ out) {
    const int row0 = blockIdx.y * 64;
    const int col0 = blockIdx.x * 64;
    __shared__ float As[16][68];
    __shared__ float Bs[16][68];
    const int tid = threadIdx.x;
    const int tx = tid & 15, ty = tid >> 4;
    float acc[4][4] = {};
    for (int k0 = 0; k0 < 900; k0 += 16) {
        __syncthreads();
        {
            int kk = tid & 15;
            int k  = k0 + kk;
            #pragma unroll
            for (int q = 0; q < 4; q++) {
                int r = (tid >> 4) + q * 16;
                int row = row0 + r;
                float v = 0.f;
                if (k < 900) {
                    if (k < 300)       v = g_agg[row * HH + k];
                    else if (k < 600)  v = g_msg_atom[row * HH + (k - 300)];
                    else               v = g_input_atom[row * HH + (k - 600)];
                }
                As[kk][r] = v;
            }
        }
        {
            int nn = tid & 63;
            int c  = col0 + nn;
            #pragma unroll
            for (int q = 0; q < 4; q++) {
                int kk = (tid >> 6) + q * 4;
                int k  = k0 + kk;
                Bs[kk][nn] = (k < 900 && c < HH) ? W[k * HH + c] : 0.f;
            }
        }
        __syncthreads();
        #pragma unroll
        for (int kk = 0; kk < 16; kk++) {
            float4 a4 = *(const float4*)&As[kk][ty * 4];
            float4 b4 = *(const float4*)&Bs[kk][tx * 4];
            float a[4] = {a4.x, a4.y, a4.z, a4.w};
            float b[4] = {b4.x, b4.y, b4.z, b4.w};
            #pragma unroll
            for (int i = 0; i < 4; i++)
                #pragma unroll
                for (int j = 0; j < 4; j++)
                    acc[i][j] += a[i] * b[j];
        }
    }
    #pragma unroll
    for (int i = 0; i < 4; i++) {
        int r = row0 + ty * 4 + i;
        #pragma unroll
        for (int j = 0; j < 4; j++) {
            int c = col0 + tx * 4 + j;
            if (c < HH) {
                float v = acc[i][j] + bias[c];
                out[r * HH + c] = v > 0.f ? v : 0.f;
            }
        }
    }
}

// ---------------------------------------------------------------------------
extern "C" void kernel_launch(void* const* d_in, const int* in_sizes, int n_in,
                              void* d_out, int out_size) {
    const float* f_atoms  = (const float*)d_in[0];
    const float* f_bonds  = (const float*)d_in[1];
    const float* adj      = (const float*)d_in[2];
    const float* W_i_atom = (const float*)d_in[3];
    const float* W_i_bond = (const float*)d_in[4];
    const float* W_h0     = (const float*)d_in[5];
    const float* W_h1     = (const float*)d_in[6];
    const float* W_o      = (const float*)d_in[7];
    const float* b_o      = (const float*)d_in[8];
    float* out = (float*)d_out;

    float *p_inbond = 0, *p_mbA = 0, *p_mbB = 0, *p_msg = 0, *p_maW = 0;
    cudaGetSymbolAddress((void**)&p_inbond, g_input_bond);
    cudaGetSymbolAddress((void**)&p_mbA, g_mbA);
    cudaGetSymbolAddress((void**)&p_mbB, g_mbB);
    cudaGetSymbolAddress((void**)&p_msg, g_msg_atom);
    cudaGetSymbolAddress((void**)&p_maW, g_maW);

    // Output layout: [atom_hiddens (2048*300) | message_bond (131072*300)].
    float* mb_final = (out_size >= AR * HH + BR * HH) ? (out + AR * HH) : p_mbB;

    k_input_atom<<<dim3(5, 32), 256>>>(f_atoms, W_i_atom);
    // input_bond = relu((adj ⊙ f_bonds) @ W_i_bond)   (K=147 -> scalar A loads)
    k_gemm_f2<BF, 1, 1><<<dim3(5, BR / 128), 128>>>(f_bonds, W_i_bond, p_inbond, HH, adj);

    // ---- depth step 0 (prev = input_bond) ----
    k_agg<<<2048, 320>>>(p_inbond);                     // msg_atom += agg(mb0)
    k_resonance2<<<32, 256>>>(adj);                     // -> g_sm
    k_gemm_f2<HH, 0, 0><<<dim3(5, AR / 128), 128>>>(p_msg, W_h0, p_maW, HH, nullptr);
    k_bondstep<1><<<dim3(5, BR / 128), 128>>>(p_inbond, W_h0, p_inbond, p_maW, adj, p_mbA);

    // ---- depth step 1 (prev = mbA) ----
    k_resonance2<<<32, 256>>>(adj);
    k_gemm_f2<HH, 0, 0><<<dim3(5, AR / 128), 128>>>(p_msg, W_h1, p_maW, HH, nullptr);
    k_bondstep<0><<<dim3(5, BR / 128), 128>>>(p_mbA, W_h1, p_inbond, p_maW, adj, mb_final);

    // ---- readout ----
    k_output<<<dim3(5, 32), 256>>>(W_o, b_o, out);
}

// round 6
// speedup vs baseline: 2.5412x; 1.2135x over previous
#include <cuda_runtime.h>
#include <cuda_bf16.h>
#include <math.h>
#include <stdint.h>

// Problem constants
#define GG 32
#define NA 64
#define HH 300
#define AF 133
#define BF 147
#define AR (GG*NA)     // 2048
#define BR (GG*NA*NA)  // 131072
#define KP 320         // padded K for bf16 planes (zero pads via zero-init)

// Scratch (zero-initialized device globals; allocation-free)
__device__ float g_input_atom[AR*HH];
__device__ float g_msg_atom[AR*HH];
__device__ float g_agg[AR*HH];
__device__ float g_maW[AR*HH];
__device__ float g_input_bond[BR*HH];   // 157 MB fp32 (ib, reused both steps)
__device__ float g_mbB[BR*HH];          // fallback mb_final
__device__ float g_sm[BR];
// bf16 hi/lo planes (pads [300,320) never written -> stay zero)
__device__ __nv_bfloat16 g_P0h[(size_t)BR*KP];
__device__ __nv_bfloat16 g_P0l[(size_t)BR*KP];
__device__ __nv_bfloat16 g_P1h[(size_t)BR*KP];
__device__ __nv_bfloat16 g_P1l[(size_t)BR*KP];
__device__ __nv_bfloat16 g_Wt0h[KP*KP];
__device__ __nv_bfloat16 g_Wt0l[KP*KP];
__device__ __nv_bfloat16 g_Wt1h[KP*KP];
__device__ __nv_bfloat16 g_Wt1l[KP*KP];

// ---------------------------------------------------------------------------
// f32x2 helpers
// ---------------------------------------------------------------------------
__device__ __forceinline__ unsigned long long pack2(float x, float y) {
    unsigned long long r;
    asm("mov.b64 %0, {%1, %2};" : "=l"(r)
        : "r"(__float_as_uint(x)), "r"(__float_as_uint(y)));
    return r;
}
__device__ __forceinline__ void ffma2(unsigned long long& d, unsigned long long a,
                                      unsigned long long b) {
    asm("fma.rn.f32x2 %0, %1, %2, %3;" : "=l"(d) : "l"(a), "l"(b), "l"(d));
}
__device__ __forceinline__ float2 unpack2(unsigned long long v) {
    unsigned lo, hi;
    asm("mov.b64 {%0, %1}, %2;" : "=r"(lo), "=r"(hi) : "l"(v));
    return make_float2(__uint_as_float(lo), __uint_as_float(hi));
}

#define MMA_BF16(c, a, b0, b1) \
    asm volatile("mma.sync.aligned.m16n8k16.row.col.f32.bf16.bf16.f32 " \
                 "{%0,%1,%2,%3}, {%4,%5,%6,%7}, {%8,%9}, {%0,%1,%2,%3};" \
                 : "+f"((c)[0]), "+f"((c)[1]), "+f"((c)[2]), "+f"((c)[3]) \
                 : "r"((a)[0]), "r"((a)[1]), "r"((a)[2]), "r"((a)[3]), \
                   "r"(b0), "r"(b1))

__device__ __forceinline__ void split_bf16(float v, __nv_bfloat16& h, __nv_bfloat16& l) {
    h = __float2bfloat16(v);
    l = __float2bfloat16(v - __bfloat162float(h));
}

// ---------------------------------------------------------------------------
// f32x2 SGEMM (input_bond + maW): C = op(A (opt row-scaled) @ W)
// Optionally emits bf16 hi/lo planes of C (row stride KP).
// ---------------------------------------------------------------------------
#define BKg 12
template<int K, int SCALED, int RELU, int EMITB>
__global__ __launch_bounds__(128, 3)
void k_gemm_f2(const float* __restrict__ A, const float* __restrict__ W,
               float* __restrict__ Co, int N, const float* __restrict__ rowScale,
               __nv_bfloat16* __restrict__ pH, __nv_bfloat16* __restrict__ pL) {
    constexpr bool A_VEC = (K % 4 == 0);
    const int row0 = blockIdx.y * 128;
    const int col0 = blockIdx.x * 64;
    __shared__ __align__(16) float As[BKg][132];
    __shared__ __align__(16) float Bs[BKg][72];
    const int tid = threadIdx.x;
    const int rg = tid >> 3;
    const int cg = tid & 7;

    int ar[3], ac4[3];
    #pragma unroll
    for (int q = 0; q < 3; q++) {
        int l = q * 128 + tid;
        ar[q]  = l / 3;
        ac4[q] = l - ar[q] * 3;
    }
    float asc[3];
    #pragma unroll
    for (int q = 0; q < 3; q++)
        asc[q] = SCALED ? rowScale[row0 + ar[q]] : 1.f;

    const int bk0  = tid >> 4;
    const int bk1  = (tid + 128) >> 4;
    const int bc4  = tid & 15;
    const bool hasB1  = (tid < 64);
    const bool bcolOK = (col0 + 4 * bc4 + 4 <= N);

    unsigned long long acc[8][4];
    #pragma unroll
    for (int i = 0; i < 8; i++)
        #pragma unroll
        for (int p = 0; p < 4; p++) acc[i][p] = 0ull;

    float4 ra[3], rb0, rb1;
    auto load_tile = [&](int k0) {
        #pragma unroll
        for (int q = 0; q < 3; q++) {
            int gk = k0 + 4 * ac4[q];
            const float* ap = &A[(size_t)(row0 + ar[q]) * K + gk];
            if (A_VEC && gk + 4 <= K) {
                ra[q] = *(const float4*)ap;
            } else {
                float v[4];
                #pragma unroll
                for (int e = 0; e < 4; e++) v[e] = (gk + e < K) ? ap[e] : 0.f;
                ra[q] = make_float4(v[0], v[1], v[2], v[3]);
            }
        }
        {
            int gk = k0 + bk0;
            if (gk < K && bcolOK)
                rb0 = *(const float4*)&W[(size_t)gk * N + col0 + 4 * bc4];
            else rb0 = make_float4(0.f, 0.f, 0.f, 0.f);
        }
        if (hasB1) {
            int gk = k0 + bk1;
            if (gk < K && bcolOK)
                rb1 = *(const float4*)&W[(size_t)gk * N + col0 + 4 * bc4];
            else rb1 = make_float4(0.f, 0.f, 0.f, 0.f);
        }
    };

    const int nIter = (K + BKg - 1) / BKg;
    load_tile(0);
    int k0 = 0;
    for (int it = 0; it < nIter; ++it) {
        __syncthreads();
        #pragma unroll
        for (int q = 0; q < 3; q++) {
            int kb = 4 * ac4[q];
            float s = asc[q];
            As[kb + 0][ar[q]] = ra[q].x * s;
            As[kb + 1][ar[q]] = ra[q].y * s;
            As[kb + 2][ar[q]] = ra[q].z * s;
            As[kb + 3][ar[q]] = ra[q].w * s;
        }
        *(float4*)&Bs[bk0][4 * bc4] = rb0;
        if (hasB1) *(float4*)&Bs[bk1][4 * bc4] = rb1;
        __syncthreads();
        if (it + 1 < nIter) load_tile(k0 + BKg);
        #pragma unroll
        for (int kk = 0; kk < BKg; ++kk) {
            float4 a0 = *(const float4*)&As[kk][rg * 8];
            float4 a1 = *(const float4*)&As[kk][rg * 8 + 4];
            ulonglong2 b01 = *(const ulonglong2*)&Bs[kk][cg * 8];
            ulonglong2 b23 = *(const ulonglong2*)&Bs[kk][cg * 8 + 4];
            float av[8] = {a0.x, a0.y, a0.z, a0.w, a1.x, a1.y, a1.z, a1.w};
            #pragma unroll
            for (int i = 0; i < 8; i++) {
                unsigned long long ap = pack2(av[i], av[i]);
                ffma2(acc[i][0], ap, b01.x);
                ffma2(acc[i][1], ap, b01.y);
                ffma2(acc[i][2], ap, b23.x);
                ffma2(acc[i][3], ap, b23.y);
            }
        }
        k0 += BKg;
    }

    const bool fastcol = (col0 + 64 <= N);
    #pragma unroll
    for (int i = 0; i < 8; i++) {
        size_t row = row0 + rg * 8 + i;
        float v[8];
        #pragma unroll
        for (int p = 0; p < 4; p++) {
            float2 f = unpack2(acc[i][p]);
            v[2 * p] = f.x; v[2 * p + 1] = f.y;
        }
        if (RELU) {
            #pragma unroll
            for (int jj = 0; jj < 8; jj++) v[jj] = fmaxf(v[jj], 0.f);
        }
        size_t base = row * N + col0 + cg * 8;
        if (fastcol) {
            *(float4*)&Co[base]     = make_float4(v[0], v[1], v[2], v[3]);
            *(float4*)&Co[base + 4] = make_float4(v[4], v[5], v[6], v[7]);
            if (EMITB) {
                __align__(16) __nv_bfloat16 hb[8], lb[8];
                #pragma unroll
                for (int jj = 0; jj < 8; jj++) split_bf16(v[jj], hb[jj], lb[jj]);
                size_t pb = row * KP + col0 + cg * 8;
                *(uint4*)&pH[pb] = *(uint4*)hb;
                *(uint4*)&pL[pb] = *(uint4*)lb;
            }
        } else {
            #pragma unroll
            for (int jj = 0; jj < 8; jj++) {
                int c = col0 + cg * 8 + jj;
                if (c < N) {
                    Co[base + jj] = v[jj];
                    if (EMITB) {
                        __nv_bfloat16 hb, lb;
                        split_bf16(v[jj], hb, lb);
                        pH[row * KP + c] = hb;
                        pL[row * KP + c] = lb;
                    }
                }
            }
        }
    }
}

// ---------------------------------------------------------------------------
// W transpose + split: Wt[n][k] (row stride KP) hi/lo from W[k*300+n]
// ---------------------------------------------------------------------------
__global__ void k_convW(const float* __restrict__ W,
                        __nv_bfloat16* __restrict__ hi, __nv_bfloat16* __restrict__ lo) {
    int n = blockIdx.x;          // 0..299
    int k = threadIdx.x;         // 0..319
    if (k < HH) {
        float v = W[(size_t)k * HH + n];
        __nv_bfloat16 h, l;
        split_bf16(v, h, l);
        hi[(size_t)n * KP + k] = h;
        lo[(size_t)n * KP + k] = l;
    }
}

// ---------------------------------------------------------------------------
// Tensor-core fused bond step (split-bf16 3-product mma.sync):
//   acc = (prev @ W)[row]   (A = hi/lo planes, B = Wt hi/lo planes)
//   val = relu(ib[g,y,x,c] + adj[g,x,y]*maW[g,y,c] - acc) * sm[(g,y),x]
//   transposed store (fp32 if STORE, bf16 planes if EMIT) + agg over y
// Block: 128 rows (g, x0..x0+1, y=0..63) x 64 cols. 256 threads = 8 warps.
// Warp (rw 0..3, cw 0..1): 32x32 tile; mma m16n8k16, mt 0..1, nt 0..3.
// ---------------------------------------------------------------------------
template<int UPDATE, int EMIT, int STORE>
__global__ __launch_bounds__(256)
void k_bondstep_mma(const __nv_bfloat16* __restrict__ pAh, const __nv_bfloat16* __restrict__ pAl,
                    const __nv_bfloat16* __restrict__ pWh, const __nv_bfloat16* __restrict__ pWl,
                    const float* __restrict__ ib, const float* __restrict__ maW,
                    const float* __restrict__ adj, float* __restrict__ mbout,
                    __nv_bfloat16* __restrict__ pOh, __nv_bfloat16* __restrict__ pOl) {
    extern __shared__ __align__(16) char smraw[];
    __nv_bfloat16 (*sAh)[40] = (__nv_bfloat16(*)[40])(smraw + 0);
    __nv_bfloat16 (*sAl)[40] = (__nv_bfloat16(*)[40])(smraw + 10240);
    __nv_bfloat16 (*sBh)[40] = (__nv_bfloat16(*)[40])(smraw + 20480);
    __nv_bfloat16 (*sBl)[40] = (__nv_bfloat16(*)[40])(smraw + 25600);
    float (*maWs)[68]        = (float(*)[68])(smraw + 30720);   // 64x68
    float (*psum)[65]        = (float(*)[65])(smraw + 48128);   // 32x65
    float (*pmax)[65]        = (float(*)[65])(smraw + 56448);
    float (*adjs)[64]        = (float(*)[64])(smraw + 64768);   // [2][64]
    float (*smvv)[64]        = (float(*)[64])(smraw + 65280);   // [2][64]

    const int row0 = blockIdx.y * 128;
    const int col0 = blockIdx.x * 64;
    const int g  = row0 >> 12;
    const int x0 = (row0 >> 6) & 63;
    const int tid = threadIdx.x;
    const int w   = tid >> 5;
    const int rw  = w & 3;
    const int cw  = w >> 2;
    const int lane = tid & 31;
    const int gid = lane >> 2;
    const int q   = lane & 3;

    // epilogue operands (visible after first mainloop __syncthreads)
    if (tid < 128) {
        int xl = tid >> 6, y = tid & 63;
        adjs[xl][y] = adj[(size_t)(g * 64 + x0 + xl) * 64 + y];
        smvv[xl][y] = g_sm[(size_t)(g * 64 + y) * 64 + x0 + xl];
    }
    for (int l = tid; l < 64 * 16; l += 256) {
        int y = l >> 4, c4 = (l & 15) * 4;
        int c = col0 + c4;
        float4 v;
        if (c + 4 <= HH) v = *(const float4*)&maW[(size_t)(g * 64 + y) * HH + c];
        else {
            float t[4];
            #pragma unroll
            for (int e = 0; e < 4; e++)
                t[e] = (c + e < HH) ? maW[(size_t)(g * 64 + y) * HH + c + e] : 0.f;
            v = make_float4(t[0], t[1], t[2], t[3]);
        }
        *(float4*)&maWs[y][c4] = v;
    }

    // fill geometry
    const int arow  = tid >> 1, apart = tid & 1;   // A: 128 rows x 32 k, 2x16B/thread/plane
    const int bn    = tid >> 2, bpart = tid & 3;   // B: 64 rows x 32 k, 1x16B/thread/plane

    float acc[2][4][4];
    #pragma unroll
    for (int mt = 0; mt < 2; mt++)
        #pragma unroll
        for (int nt = 0; nt < 4; nt++)
            #pragma unroll
            for (int e = 0; e < 4; e++) acc[mt][nt][e] = 0.f;

    uint4 rAh[2], rAl[2], rBh, rBl;
    auto load_tile = [&](int k0) {
        const __nv_bfloat16* bAh = pAh + (size_t)(row0 + arow) * KP + k0 + apart * 16;
        const __nv_bfloat16* bAl = pAl + (size_t)(row0 + arow) * KP + k0 + apart * 16;
        rAh[0] = *(const uint4*)bAh;  rAh[1] = *(const uint4*)(bAh + 8);
        rAl[0] = *(const uint4*)bAl;  rAl[1] = *(const uint4*)(bAl + 8);
        const __nv_bfloat16* bBh = pWh + (size_t)(col0 + bn) * KP + k0 + bpart * 8;
        const __nv_bfloat16* bBl = pWl + (size_t)(col0 + bn) * KP + k0 + bpart * 8;
        rBh = *(const uint4*)bBh;
        rBl = *(const uint4*)bBl;
    };

    load_tile(0);
    int k0 = 0;
    for (int it = 0; it < KP / 32; ++it) {
        __syncthreads();
        *(uint4*)&sAh[arow][apart * 16]     = rAh[0];
        *(uint4*)&sAh[arow][apart * 16 + 8] = rAh[1];
        *(uint4*)&sAl[arow][apart * 16]     = rAl[0];
        *(uint4*)&sAl[arow][apart * 16 + 8] = rAl[1];
        *(uint4*)&sBh[bn][bpart * 8] = rBh;
        *(uint4*)&sBl[bn][bpart * 8] = rBl;
        __syncthreads();
        if (it + 1 < KP / 32) load_tile(k0 + 32);
        #pragma unroll
        for (int ks = 0; ks < 2; ++ks) {
            const int kb = ks * 16 + q * 2;
            uint32_t afh[2][4], afl[2][4];
            #pragma unroll
            for (int mt = 0; mt < 2; mt++) {
                int r0 = rw * 32 + mt * 16 + gid;
                afh[mt][0] = *(const uint32_t*)&sAh[r0][kb];
                afh[mt][1] = *(const uint32_t*)&sAh[r0 + 8][kb];
                afh[mt][2] = *(const uint32_t*)&sAh[r0][kb + 8];
                afh[mt][3] = *(const uint32_t*)&sAh[r0 + 8][kb + 8];
                afl[mt][0] = *(const uint32_t*)&sAl[r0][kb];
                afl[mt][1] = *(const uint32_t*)&sAl[r0 + 8][kb];
                afl[mt][2] = *(const uint32_t*)&sAl[r0][kb + 8];
                afl[mt][3] = *(const uint32_t*)&sAl[r0 + 8][kb + 8];
            }
            #pragma unroll
            for (int nt = 0; nt < 4; nt++) {
                int nn = cw * 32 + nt * 8 + gid;
                uint32_t bh0 = *(const uint32_t*)&sBh[nn][kb];
                uint32_t bh1 = *(const uint32_t*)&sBh[nn][kb + 8];
                uint32_t bl0 = *(const uint32_t*)&sBl[nn][kb];
                uint32_t bl1 = *(const uint32_t*)&sBl[nn][kb + 8];
                #pragma unroll
                for (int mt = 0; mt < 2; mt++) {
                    MMA_BF16(acc[mt][nt], afh[mt], bh0, bh1);
                    MMA_BF16(acc[mt][nt], afh[mt], bl0, bl1);
                    MMA_BF16(acc[mt][nt], afl[mt], bh0, bh1);
                }
            }
        }
        k0 += 32;
    }

    // ---- fused epilogue on fragment layout ----
    float tsum[4][2], tmax[4][2];
    #pragma unroll
    for (int nt = 0; nt < 4; nt++)
        #pragma unroll
        for (int p = 0; p < 2; p++) { tsum[nt][p] = 0.f; tmax[nt][p] = -INFINITY; }

    #pragma unroll
    for (int mt = 0; mt < 2; mt++) {
        #pragma unroll
        for (int rp = 0; rp < 2; rp++) {
            int lr = rw * 32 + mt * 16 + gid + rp * 8;
            int xl = lr >> 6, y = lr & 63;
            int x  = x0 + xl;
            float a = adjs[xl][y];
            float wv = smvv[xl][y];
            size_t brow = (size_t)(g * 64 + y) * 64 + x;
            #pragma unroll
            for (int nt = 0; nt < 4; nt++) {
                int c = cw * 32 + nt * 8 + q * 2;
                int h = col0 + c;
                if (h < HH) {
                    size_t ob = brow * HH + h;
                    float2 ibv = *(const float2*)&ib[ob];
                    float v0 = fmaxf(ibv.x + a * maWs[y][c]     - acc[mt][nt][rp * 2 + 0], 0.f) * wv;
                    float v1 = fmaxf(ibv.y + a * maWs[y][c + 1] - acc[mt][nt][rp * 2 + 1], 0.f) * wv;
                    if (STORE) *(float2*)&mbout[ob] = make_float2(v0, v1);
                    if (EMIT) {
                        __nv_bfloat16 h0, l0, h1, l1;
                        split_bf16(v0, h0, l0);
                        split_bf16(v1, h1, l1);
                        size_t pb = brow * KP + h;
                        __nv_bfloat162 hp; hp.x = h0; hp.y = h1;
                        __nv_bfloat162 lp; lp.x = l0; lp.y = l1;
                        *(__nv_bfloat162*)&pOh[pb] = hp;
                        *(__nv_bfloat162*)&pOl[pb] = lp;
                    }
                    tsum[nt][0] += v0;  tmax[nt][0] = fmaxf(tmax[nt][0], v0);
                    tsum[nt][1] += v1;  tmax[nt][1] = fmaxf(tmax[nt][1], v1);
                }
            }
        }
    }
    // per-lane partials -> smem (unique slot per (rw,gid,c))
    {
        int slot = rw * 8 + gid;
        #pragma unroll
        for (int nt = 0; nt < 4; nt++) {
            int c = cw * 32 + nt * 8 + q * 2;
            psum[slot][c]     = tsum[nt][0];
            psum[slot][c + 1] = tsum[nt][1];
            pmax[slot][c]     = tmax[nt][0];
            pmax[slot][c + 1] = tmax[nt][1];
        }
    }
    __syncthreads();
    if (tid < 128) {
        int xl = tid >> 6, c = tid & 63;
        if (col0 + c < HH) {
            float s = 0.f, m = -INFINITY;
            #pragma unroll
            for (int r = 0; r < 16; r++) {
                s += psum[xl * 16 + r][c];
                m = fmaxf(m, pmax[xl * 16 + r][c]);
            }
            float aggv = s * (1.f / (1.f + expf(-m)));
            size_t idx = (size_t)(g * 64 + x0 + xl) * HH + col0 + c;
            if (UPDATE) g_msg_atom[idx] += aggv;
            else        g_agg[idx] = aggv;
        }
    }
}

// ---------------------------------------------------------------------------
// input_atom = relu(f_atoms @ W_i_atom) (also -> msg_atom)
// ---------------------------------------------------------------------------
__global__ void k_input_atom(const float* __restrict__ A, const float* __restrict__ W) {
    const int row0 = blockIdx.y * 64;
    const int col0 = blockIdx.x * 64;
    __shared__ float As[16][68];
    __shared__ float Bs[16][68];
    const int tid = threadIdx.x;
    const int tx = tid & 15, ty = tid >> 4;
    float acc[4][4] = {};
    for (int k0 = 0; k0 < AF; k0 += 16) {
        __syncthreads();
        {
            int kk = tid & 15;
            int k  = k0 + kk;
            #pragma unroll
            for (int qq = 0; qq < 4; qq++) {
                int r = (tid >> 4) + qq * 16;
                As[kk][r] = (k < AF) ? A[(row0 + r) * AF + k] : 0.f;
            }
        }
        {
            int nn = tid & 63;
            int c  = col0 + nn;
            #pragma unroll
            for (int qq = 0; qq < 4; qq++) {
                int kk = (tid >> 6) + qq * 4;
                int k  = k0 + kk;
                Bs[kk][nn] = (k < AF && c < HH) ? W[k * HH + c] : 0.f;
            }
        }
        __syncthreads();
        #pragma unroll
        for (int kk = 0; kk < 16; kk++) {
            float4 a4 = *(const float4*)&As[kk][ty * 4];
            float4 b4 = *(const float4*)&Bs[kk][tx * 4];
            float a[4] = {a4.x, a4.y, a4.z, a4.w};
            float b[4] = {b4.x, b4.y, b4.z, b4.w};
            #pragma unroll
            for (int i = 0; i < 4; i++)
                #pragma unroll
                for (int j = 0; j < 4; j++)
                    acc[i][j] += a[i] * b[j];
        }
    }
    #pragma unroll
    for (int i = 0; i < 4; i++) {
        int r = row0 + ty * 4 + i;
        #pragma unroll
        for (int j = 0; j < 4; j++) {
            int c = col0 + tx * 4 + j;
            if (c < HH) {
                float v = acc[i][j];
                v = v > 0.f ? v : 0.f;
                g_input_atom[r * HH + c] = v;
                g_msg_atom[r * HH + c]   = v;
            }
        }
    }
}

// ---------------------------------------------------------------------------
__global__ void k_agg(const float* __restrict__ mb) {
    int gm = blockIdx.x;
    int h = threadIdx.x;
    if (h >= HH) return;
    int g = gm >> 6, m = gm & 63;
    const float* base = mb + ((size_t)(g * 64) * 64 + m) * HH + h;
    float s = 0.f, mx = -INFINITY;
    #pragma unroll 4
    for (int n = 0; n < 64; n++) {
        float v = base[(size_t)n * 64 * HH];
        s += v;
        mx = fmaxf(mx, v);
    }
    float a = s * (1.f / (1.f + expf(-mx)));
    g_msg_atom[gm * HH + h] += a;
}

// ---------------------------------------------------------------------------
__global__ void k_resonance2(const float* __restrict__ adj) {
    int g = blockIdx.x;
    __shared__ float mt[64][101];
    __shared__ float rr[64][65];
    int tid = threadIdx.x;
    int tx = tid & 15, ty = tid >> 4;
    float acc[4][4] = {};
    for (int c = 0; c < 3; ++c) {
        __syncthreads();
        for (int l = tid; l < 6400; l += 256) {
            int r = l / 100, k = l - r * 100;
            mt[r][k] = g_msg_atom[((size_t)(g * 64 + r)) * 300 + c * 100 + k];
        }
        __syncthreads();
        for (int kk = 0; kk < 100; ++kk) {
            float a[4], b[4];
            #pragma unroll
            for (int i = 0; i < 4; i++) a[i] = mt[ty * 4 + i][kk];
            #pragma unroll
            for (int j = 0; j < 4; j++) b[j] = mt[tx * 4 + j][kk];
            #pragma unroll
            for (int i = 0; i < 4; i++)
                #pragma unroll
                for (int j = 0; j < 4; j++)
                    acc[i][j] += a[i] * b[j];
        }
    }
    #pragma unroll
    for (int i = 0; i < 4; i++)
        #pragma unroll
        for (int j = 0; j < 4; j++)
            rr[ty * 4 + i][tx * 4 + j] = acc[i][j];
    __syncthreads();
    if (tid < 64) {
        int m = tid;
        float mxv = -INFINITY;
        for (int n = 0; n < 64; n++) {
            float v = rr[n][m] * adj[((size_t)(g * 64 + n)) * 64 + m];
            rr[n][m] = v;
            mxv = fmaxf(mxv, v);
        }
        float sum = 0.f;
        for (int n = 0; n < 64; n++) {
            float e = expf(rr[n][m] - mxv);
            rr[n][m] = e;
            sum += e;
        }
        float inv = 1.f / sum;
        for (int n = 0; n < 64; n++)
            g_sm[(size_t)(g * 64 + n) * 64 + m] = rr[n][m] * inv;
    }
}

// ---------------------------------------------------------------------------
__global__ void k_output(const float* __restrict__ W, const float* __restrict__ bias,
                         float* __restrict__ out) {
    const int row0 = blockIdx.y * 64;
    const int col0 = blockIdx.x * 64;
    __shared__ float As[16][68];
    __shared__ float Bs[16][68];
    const int tid = threadIdx.x;
    const int tx = tid & 15, ty = tid >> 4;
    float acc[4][4] = {};
    for (int k0 = 0; k0 < 900; k0 += 16) {
        __syncthreads();
        {
            int kk = tid & 15;
            int k  = k0 + kk;
            #pragma unroll
            for (int qq = 0; qq < 4; qq++) {
                int r = (tid >> 4) + qq * 16;
                int row = row0 + r;
                float v = 0.f;
                if (k < 900) {
                    if (k < 300)       v = g_agg[row * HH + k];
                    else if (k < 600)  v = g_msg_atom[row * HH + (k - 300)];
                    else               v = g_input_atom[row * HH + (k - 600)];
                }
                As[kk][r] = v;
            }
        }
        {
            int nn = tid & 63;
            int c  = col0 + nn;
            #pragma unroll
            for (int qq = 0; qq < 4; qq++) {
                int kk = (tid >> 6) + qq * 4;
                int k  = k0 + kk;
                Bs[kk][nn] = (k < 900 && c < HH) ? W[k * HH + c] : 0.f;
            }
        }
        __syncthreads();
        #pragma unroll
        for (int kk = 0; kk < 16; kk++) {
            float4 a4 = *(const float4*)&As[kk][ty * 4];
            float4 b4 = *(const float4*)&Bs[kk][tx * 4];
            float a[4] = {a4.x, a4.y, a4.z, a4.w};
            float b[4] = {b4.x, b4.y, b4.z, b4.w};
            #pragma unroll
            for (int i = 0; i < 4; i++)
                #pragma unroll
                for (int j = 0; j < 4; j++)
                    acc[i][j] += a[i] * b[j];
        }
    }
    #pragma unroll
    for (int i = 0; i < 4; i++) {
        int r = row0 + ty * 4 + i;
        #pragma unroll
        for (int j = 0; j < 4; j++) {
            int c = col0 + tx * 4 + j;
            if (c < HH) {
                float v = acc[i][j] + bias[c];
                out[r * HH + c] = v > 0.f ? v : 0.f;
            }
        }
    }
}

// ---------------------------------------------------------------------------
extern "C" void kernel_launch(void* const* d_in, const int* in_sizes, int n_in,
                              void* d_out, int out_size) {
    const float* f_atoms  = (const float*)d_in[0];
    const float* f_bonds  = (const float*)d_in[1];
    const float* adj      = (const float*)d_in[2];
    const float* W_i_atom = (const float*)d_in[3];
    const float* W_i_bond = (const float*)d_in[4];
    const float* W_h0     = (const float*)d_in[5];
    const float* W_h1     = (const float*)d_in[6];
    const float* W_o      = (const float*)d_in[7];
    const float* b_o      = (const float*)d_in[8];
    float* out = (float*)d_out;

    float *p_inbond = 0, *p_mbB = 0, *p_msg = 0, *p_maW = 0;
    __nv_bfloat16 *p0h = 0, *p0l = 0, *p1h = 0, *p1l = 0;
    __nv_bfloat16 *wt0h = 0, *wt0l = 0, *wt1h = 0, *wt1l = 0;
    cudaGetSymbolAddress((void**)&p_inbond, g_input_bond);
    cudaGetSymbolAddress((void**)&p_mbB, g_mbB);
    cudaGetSymbolAddress((void**)&p_msg, g_msg_atom);
    cudaGetSymbolAddress((void**)&p_maW, g_maW);
    cudaGetSymbolAddress((void**)&p0h, g_P0h);
    cudaGetSymbolAddress((void**)&p0l, g_P0l);
    cudaGetSymbolAddress((void**)&p1h, g_P1h);
    cudaGetSymbolAddress((void**)&p1l, g_P1l);
    cudaGetSymbolAddress((void**)&wt0h, g_Wt0h);
    cudaGetSymbolAddress((void**)&wt0l, g_Wt0l);
    cudaGetSymbolAddress((void**)&wt1h, g_Wt1h);
    cudaGetSymbolAddress((void**)&wt1l, g_Wt1l);

    float* mb_final = (out_size >= AR * HH + BR * HH) ? (out + AR * HH) : p_mbB;

    const int SMEM_MMA = 66560;
    cudaFuncSetAttribute(k_bondstep_mma<1, 1, 0>,
                         cudaFuncAttributeMaxDynamicSharedMemorySize, SMEM_MMA);
    cudaFuncSetAttribute(k_bondstep_mma<0, 0, 1>,
                         cudaFuncAttributeMaxDynamicSharedMemorySize, SMEM_MMA);

    k_input_atom<<<dim3(5, 32), 256>>>(f_atoms, W_i_atom);
    k_convW<<<HH, KP>>>(W_h0, wt0h, wt0l);
    k_convW<<<HH, KP>>>(W_h1, wt1h, wt1l);
    // input_bond = relu((adj ⊙ f_bonds) @ W_i_bond), fp32 + bf16 planes P0
    k_gemm_f2<BF, 1, 1, 1><<<dim3(5, BR / 128), 128>>>(f_bonds, W_i_bond, p_inbond, HH,
                                                       adj, p0h, p0l);

    // ---- depth step 0 (prev = input_bond) ----
    k_agg<<<2048, 320>>>(p_inbond);
    k_resonance2<<<32, 256>>>(adj);
    k_gemm_f2<HH, 0, 0, 0><<<dim3(5, AR / 128), 128>>>(p_msg, W_h0, p_maW, HH,
                                                       nullptr, nullptr, nullptr);
    k_bondstep_mma<1, 1, 0><<<dim3(5, BR / 128), 256, SMEM_MMA>>>(
        p0h, p0l, wt0h, wt0l, p_inbond, p_maW, adj, mb_final, p1h, p1l);

    // ---- depth step 1 (prev = mbA planes) ----
    k_resonance2<<<32, 256>>>(adj);
    k_gemm_f2<HH, 0, 0, 0><<<dim3(5, AR / 128), 128>>>(p_msg, W_h1, p_maW, HH,
                                                       nullptr, nullptr, nullptr);
    k_bondstep_mma<0, 0, 1><<<dim3(5, BR / 128), 256, SMEM_MMA>>>(
        p1h, p1l, wt1h, wt1l, p_inbond, p_maW, adj, mb_final, nullptr, nullptr);

    // ---- readout ----
    k_output<<<dim3(5, 32), 256>>>(W_o, b_o, out);
}

// round 7
// speedup vs baseline: 3.0129x; 1.1856x over previous
#include <cuda_runtime.h>
#include <cuda_bf16.h>
#include <math.h>
#include <stdint.h>

// Problem constants
#define GG 32
#define NA 64
#define HH 300
#define AF 133
#define BF 147
#define AR (GG*NA)     // 2048
#define BR (GG*NA*NA)  // 131072
#define KP 320         // padded K for bf16 planes (zero pads via zero-init)

// Scratch (zero-initialized device globals; allocation-free)
__device__ float g_input_atom[AR*HH];
__device__ float g_msg_atom[AR*HH];
__device__ float g_agg[AR*HH];
__device__ float g_maW[AR*HH];
__device__ float g_input_bond[BR*HH];   // 157 MB fp32 (zero rows stay zero-init)
__device__ float g_mbB[BR*HH];          // fallback mb_final
__device__ float g_sm[BR];
__device__ int   g_cnt;
__device__ int   g_rows[BR];
// bf16 hi/lo planes (pads + zero rows never written -> stay zero)
__device__ __nv_bfloat16 g_P0h[(size_t)BR*KP];
__device__ __nv_bfloat16 g_P0l[(size_t)BR*KP];
__device__ __nv_bfloat16 g_P1h[(size_t)BR*KP];
__device__ __nv_bfloat16 g_P1l[(size_t)BR*KP];
__device__ __nv_bfloat16 g_Wt0h[KP*KP];
__device__ __nv_bfloat16 g_Wt0l[KP*KP];
__device__ __nv_bfloat16 g_Wt1h[KP*KP];
__device__ __nv_bfloat16 g_Wt1l[KP*KP];

// ---------------------------------------------------------------------------
// f32x2 helpers
// ---------------------------------------------------------------------------
__device__ __forceinline__ unsigned long long pack2(float x, float y) {
    unsigned long long r;
    asm("mov.b64 %0, {%1, %2};" : "=l"(r)
        : "r"(__float_as_uint(x)), "r"(__float_as_uint(y)));
    return r;
}
__device__ __forceinline__ void ffma2(unsigned long long& d, unsigned long long a,
                                      unsigned long long b) {
    asm("fma.rn.f32x2 %0, %1, %2, %3;" : "=l"(d) : "l"(a), "l"(b), "l"(d));
}
__device__ __forceinline__ float2 unpack2(unsigned long long v) {
    unsigned lo, hi;
    asm("mov.b64 {%0, %1}, %2;" : "=r"(lo), "=r"(hi) : "l"(v));
    return make_float2(__uint_as_float(lo), __uint_as_float(hi));
}

#define MMA_BF16(c, a, b0, b1) \
    asm volatile("mma.sync.aligned.m16n8k16.row.col.f32.bf16.bf16.f32 " \
                 "{%0,%1,%2,%3}, {%4,%5,%6,%7}, {%8,%9}, {%0,%1,%2,%3};" \
                 : "+f"((c)[0]), "+f"((c)[1]), "+f"((c)[2]), "+f"((c)[3]) \
                 : "r"((a)[0]), "r"((a)[1]), "r"((a)[2]), "r"((a)[3]), \
                   "r"(b0), "r"(b1))

__device__ __forceinline__ void split_bf16(float v, __nv_bfloat16& h, __nv_bfloat16& l) {
    h = __float2bfloat16(v);
    l = __float2bfloat16(v - __bfloat162float(h));
}

// ---------------------------------------------------------------------------
// Sparse row compaction (adj is binary; ~30% density)
// ---------------------------------------------------------------------------
__global__ void k_reset() { if (threadIdx.x == 0) g_cnt = 0; }

__global__ void k_compact(const float* __restrict__ adj) {
    int i = blockIdx.x * 256 + threadIdx.x;
    if (i < BR && adj[i] != 0.f) {
        int idx = atomicAdd(&g_cnt, 1);
        g_rows[idx] = i;
    }
}

// ---------------------------------------------------------------------------
// Indexed input_bond GEMM over compacted rows only:
// ib[row] = relu(f_bonds[row] @ W_i_bond), also emits bf16 hi/lo planes.
// (adj==1 for all compacted rows, so no scaling needed.)
// ---------------------------------------------------------------------------
#define BKg 12
__global__ __launch_bounds__(128, 3)
void k_inbond_idx(const float* __restrict__ A, const float* __restrict__ W,
                  float* __restrict__ Co,
                  __nv_bfloat16* __restrict__ pH, __nv_bfloat16* __restrict__ pL) {
    const int cnt = g_cnt;
    const int row0 = blockIdx.y * 128;
    if (row0 >= cnt) return;
    const int col0 = blockIdx.x * 64;
    __shared__ __align__(16) float As[BKg][132];
    __shared__ __align__(16) float Bs[BKg][72];
    const int tid = threadIdx.x;
    const int rg = tid >> 3;
    const int cg = tid & 7;

    int ar[3], ac4[3], ridx[3];
    #pragma unroll
    for (int q = 0; q < 3; q++) {
        int l = q * 128 + tid;
        ar[q]  = l / 3;
        ac4[q] = l - ar[q] * 3;
        int slot = row0 + ar[q];
        ridx[q] = (slot < cnt) ? g_rows[slot] : -1;
    }

    const int bk0  = tid >> 4;
    const int bk1  = (tid + 128) >> 4;
    const int bc4  = tid & 15;
    const bool hasB1  = (tid < 64);
    const bool bcolOK = (col0 + 4 * bc4 + 4 <= HH);

    unsigned long long acc[8][4];
    #pragma unroll
    for (int i = 0; i < 8; i++)
        #pragma unroll
        for (int p = 0; p < 4; p++) acc[i][p] = 0ull;

    float4 ra[3], rb0, rb1;
    auto load_tile = [&](int k0) {
        #pragma unroll
        for (int q = 0; q < 3; q++) {
            int gk = k0 + 4 * ac4[q];
            float v[4] = {0.f, 0.f, 0.f, 0.f};
            if (ridx[q] >= 0) {
                const float* ap = &A[(size_t)ridx[q] * BF + gk];
                #pragma unroll
                for (int e = 0; e < 4; e++) if (gk + e < BF) v[e] = ap[e];
            }
            ra[q] = make_float4(v[0], v[1], v[2], v[3]);
        }
        {
            int gk = k0 + bk0;
            if (gk < BF && bcolOK)
                rb0 = *(const float4*)&W[(size_t)gk * HH + col0 + 4 * bc4];
            else rb0 = make_float4(0.f, 0.f, 0.f, 0.f);
        }
        if (hasB1) {
            int gk = k0 + bk1;
            if (gk < BF && bcolOK)
                rb1 = *(const float4*)&W[(size_t)gk * HH + col0 + 4 * bc4];
            else rb1 = make_float4(0.f, 0.f, 0.f, 0.f);
        }
    };

    const int nIter = (BF + BKg - 1) / BKg;
    load_tile(0);
    int k0 = 0;
    for (int it = 0; it < nIter; ++it) {
        __syncthreads();
        #pragma unroll
        for (int q = 0; q < 3; q++) {
            int kb = 4 * ac4[q];
            As[kb + 0][ar[q]] = ra[q].x;
            As[kb + 1][ar[q]] = ra[q].y;
            As[kb + 2][ar[q]] = ra[q].z;
            As[kb + 3][ar[q]] = ra[q].w;
        }
        *(float4*)&Bs[bk0][4 * bc4] = rb0;
        if (hasB1) *(float4*)&Bs[bk1][4 * bc4] = rb1;
        __syncthreads();
        if (it + 1 < nIter) load_tile(k0 + BKg);
        #pragma unroll
        for (int kk = 0; kk < BKg; ++kk) {
            float4 a0 = *(const float4*)&As[kk][rg * 8];
            float4 a1 = *(const float4*)&As[kk][rg * 8 + 4];
            ulonglong2 b01 = *(const ulonglong2*)&Bs[kk][cg * 8];
            ulonglong2 b23 = *(const ulonglong2*)&Bs[kk][cg * 8 + 4];
            float av[8] = {a0.x, a0.y, a0.z, a0.w, a1.x, a1.y, a1.z, a1.w};
            #pragma unroll
            for (int i = 0; i < 8; i++) {
                unsigned long long ap = pack2(av[i], av[i]);
                ffma2(acc[i][0], ap, b01.x);
                ffma2(acc[i][1], ap, b01.y);
                ffma2(acc[i][2], ap, b23.x);
                ffma2(acc[i][3], ap, b23.y);
            }
        }
        k0 += BKg;
    }

    const bool fastcol = (col0 + 64 <= HH);
    #pragma unroll
    for (int i = 0; i < 8; i++) {
        int slot = row0 + rg * 8 + i;
        if (slot >= cnt) continue;
        size_t row = g_rows[slot];
        float v[8];
        #pragma unroll
        for (int p = 0; p < 4; p++) {
            float2 f = unpack2(acc[i][p]);
            v[2 * p] = f.x; v[2 * p + 1] = f.y;
        }
        #pragma unroll
        for (int jj = 0; jj < 8; jj++) v[jj] = fmaxf(v[jj], 0.f);
        size_t base = row * HH + col0 + cg * 8;
        if (fastcol) {
            *(float4*)&Co[base]     = make_float4(v[0], v[1], v[2], v[3]);
            *(float4*)&Co[base + 4] = make_float4(v[4], v[5], v[6], v[7]);
            __align__(16) __nv_bfloat16 hb[8], lb[8];
            #pragma unroll
            for (int jj = 0; jj < 8; jj++) split_bf16(v[jj], hb[jj], lb[jj]);
            size_t pb = row * KP + col0 + cg * 8;
            *(uint4*)&pH[pb] = *(uint4*)hb;
            *(uint4*)&pL[pb] = *(uint4*)lb;
        } else {
            #pragma unroll
            for (int jj = 0; jj < 8; jj++) {
                int c = col0 + cg * 8 + jj;
                if (c < HH) {
                    Co[base + jj] = v[jj];
                    __nv_bfloat16 hb, lb;
                    split_bf16(v[jj], hb, lb);
                    pH[row * KP + c] = hb;
                    pL[row * KP + c] = lb;
                }
            }
        }
    }
}

// ---------------------------------------------------------------------------
// f32x2 SGEMM (maW only now): C = A @ W
// ---------------------------------------------------------------------------
template<int K>
__global__ __launch_bounds__(128, 3)
void k_gemm_f2(const float* __restrict__ A, const float* __restrict__ W,
               float* __restrict__ Co, int N) {
    const int row0 = blockIdx.y * 128;
    const int col0 = blockIdx.x * 64;
    __shared__ __align__(16) float As[BKg][132];
    __shared__ __align__(16) float Bs[BKg][72];
    const int tid = threadIdx.x;
    const int rg = tid >> 3;
    const int cg = tid & 7;

    int ar[3], ac4[3];
    #pragma unroll
    for (int q = 0; q < 3; q++) {
        int l = q * 128 + tid;
        ar[q]  = l / 3;
        ac4[q] = l - ar[q] * 3;
    }
    const int bk0  = tid >> 4;
    const int bk1  = (tid + 128) >> 4;
    const int bc4  = tid & 15;
    const bool hasB1  = (tid < 64);
    const bool bcolOK = (col0 + 4 * bc4 + 4 <= N);

    unsigned long long acc[8][4];
    #pragma unroll
    for (int i = 0; i < 8; i++)
        #pragma unroll
        for (int p = 0; p < 4; p++) acc[i][p] = 0ull;

    float4 ra[3], rb0, rb1;
    auto load_tile = [&](int k0) {
        #pragma unroll
        for (int q = 0; q < 3; q++)
            ra[q] = *(const float4*)&A[(size_t)(row0 + ar[q]) * K + k0 + 4 * ac4[q]];
        {
            int gk = k0 + bk0;
            rb0 = (gk < K && bcolOK) ? *(const float4*)&W[(size_t)gk * N + col0 + 4 * bc4]
                                     : make_float4(0.f, 0.f, 0.f, 0.f);
        }
        if (hasB1) {
            int gk = k0 + bk1;
            rb1 = (gk < K && bcolOK) ? *(const float4*)&W[(size_t)gk * N + col0 + 4 * bc4]
                                     : make_float4(0.f, 0.f, 0.f, 0.f);
        }
    };

    const int nIter = (K + BKg - 1) / BKg;
    load_tile(0);
    int k0 = 0;
    for (int it = 0; it < nIter; ++it) {
        __syncthreads();
        #pragma unroll
        for (int q = 0; q < 3; q++) {
            int kb = 4 * ac4[q];
            As[kb + 0][ar[q]] = ra[q].x;
            As[kb + 1][ar[q]] = ra[q].y;
            As[kb + 2][ar[q]] = ra[q].z;
            As[kb + 3][ar[q]] = ra[q].w;
        }
        *(float4*)&Bs[bk0][4 * bc4] = rb0;
        if (hasB1) *(float4*)&Bs[bk1][4 * bc4] = rb1;
        __syncthreads();
        if (it + 1 < nIter) load_tile(k0 + BKg);
        #pragma unroll
        for (int kk = 0; kk < BKg; ++kk) {
            float4 a0 = *(const float4*)&As[kk][rg * 8];
            float4 a1 = *(const float4*)&As[kk][rg * 8 + 4];
            ulonglong2 b01 = *(const ulonglong2*)&Bs[kk][cg * 8];
            ulonglong2 b23 = *(const ulonglong2*)&Bs[kk][cg * 8 + 4];
            float av[8] = {a0.x, a0.y, a0.z, a0.w, a1.x, a1.y, a1.z, a1.w};
            #pragma unroll
            for (int i = 0; i < 8; i++) {
                unsigned long long ap = pack2(av[i], av[i]);
                ffma2(acc[i][0], ap, b01.x);
                ffma2(acc[i][1], ap, b01.y);
                ffma2(acc[i][2], ap, b23.x);
                ffma2(acc[i][3], ap, b23.y);
            }
        }
        k0 += BKg;
    }

    const bool fastcol = (col0 + 64 <= N);
    #pragma unroll
    for (int i = 0; i < 8; i++) {
        size_t row = row0 + rg * 8 + i;
        float v[8];
        #pragma unroll
        for (int p = 0; p < 4; p++) {
            float2 f = unpack2(acc[i][p]);
            v[2 * p] = f.x; v[2 * p + 1] = f.y;
        }
        size_t base = row * N + col0 + cg * 8;
        if (fastcol) {
            *(float4*)&Co[base]     = make_float4(v[0], v[1], v[2], v[3]);
            *(float4*)&Co[base + 4] = make_float4(v[4], v[5], v[6], v[7]);
        } else {
            #pragma unroll
            for (int jj = 0; jj < 8; jj++)
                if (col0 + cg * 8 + jj < N) Co[base + jj] = v[jj];
        }
    }
}

// ---------------------------------------------------------------------------
// W transpose + split
// ---------------------------------------------------------------------------
__global__ void k_convW(const float* __restrict__ W,
                        __nv_bfloat16* __restrict__ hi, __nv_bfloat16* __restrict__ lo) {
    int n = blockIdx.x;
    int k = threadIdx.x;
    if (k < HH) {
        float v = W[(size_t)k * HH + n];
        __nv_bfloat16 h, l;
        split_bf16(v, h, l);
        hi[(size_t)n * KP + k] = h;
        lo[(size_t)n * KP + k] = l;
    }
}

// ---------------------------------------------------------------------------
// Tensor-core fused bond step (unchanged from round 6 — passing)
// ---------------------------------------------------------------------------
template<int UPDATE, int EMIT, int STORE>
__global__ __launch_bounds__(256)
void k_bondstep_mma(const __nv_bfloat16* __restrict__ pAh, const __nv_bfloat16* __restrict__ pAl,
                    const __nv_bfloat16* __restrict__ pWh, const __nv_bfloat16* __restrict__ pWl,
                    const float* __restrict__ ib, const float* __restrict__ maW,
                    const float* __restrict__ adj, float* __restrict__ mbout,
                    __nv_bfloat16* __restrict__ pOh, __nv_bfloat16* __restrict__ pOl) {
    extern __shared__ __align__(16) char smraw[];
    __nv_bfloat16 (*sAh)[40] = (__nv_bfloat16(*)[40])(smraw + 0);
    __nv_bfloat16 (*sAl)[40] = (__nv_bfloat16(*)[40])(smraw + 10240);
    __nv_bfloat16 (*sBh)[40] = (__nv_bfloat16(*)[40])(smraw + 20480);
    __nv_bfloat16 (*sBl)[40] = (__nv_bfloat16(*)[40])(smraw + 25600);
    float (*maWs)[68]        = (float(*)[68])(smraw + 30720);
    float (*psum)[65]        = (float(*)[65])(smraw + 48128);
    float (*pmax)[65]        = (float(*)[65])(smraw + 56448);
    float (*adjs)[64]        = (float(*)[64])(smraw + 64768);
    float (*smvv)[64]        = (float(*)[64])(smraw + 65280);

    const int row0 = blockIdx.y * 128;
    const int col0 = blockIdx.x * 64;
    const int g  = row0 >> 12;
    const int x0 = (row0 >> 6) & 63;
    const int tid = threadIdx.x;
    const int w   = tid >> 5;
    const int rw  = w & 3;
    const int cw  = w >> 2;
    const int lane = tid & 31;
    const int gid = lane >> 2;
    const int q   = lane & 3;

    if (tid < 128) {
        int xl = tid >> 6, y = tid & 63;
        adjs[xl][y] = adj[(size_t)(g * 64 + x0 + xl) * 64 + y];
        smvv[xl][y] = g_sm[(size_t)(g * 64 + y) * 64 + x0 + xl];
    }
    for (int l = tid; l < 64 * 16; l += 256) {
        int y = l >> 4, c4 = (l & 15) * 4;
        int c = col0 + c4;
        float4 v;
        if (c + 4 <= HH) v = *(const float4*)&maW[(size_t)(g * 64 + y) * HH + c];
        else {
            float t[4];
            #pragma unroll
            for (int e = 0; e < 4; e++)
                t[e] = (c + e < HH) ? maW[(size_t)(g * 64 + y) * HH + c + e] : 0.f;
            v = make_float4(t[0], t[1], t[2], t[3]);
        }
        *(float4*)&maWs[y][c4] = v;
    }

    const int arow  = tid >> 1, apart = tid & 1;
    const int bn    = tid >> 2, bpart = tid & 3;

    float acc[2][4][4];
    #pragma unroll
    for (int mt = 0; mt < 2; mt++)
        #pragma unroll
        for (int nt = 0; nt < 4; nt++)
            #pragma unroll
            for (int e = 0; e < 4; e++) acc[mt][nt][e] = 0.f;

    uint4 rAh[2], rAl[2], rBh, rBl;
    auto load_tile = [&](int k0) {
        const __nv_bfloat16* bAh = pAh + (size_t)(row0 + arow) * KP + k0 + apart * 16;
        const __nv_bfloat16* bAl = pAl + (size_t)(row0 + arow) * KP + k0 + apart * 16;
        rAh[0] = *(const uint4*)bAh;  rAh[1] = *(const uint4*)(bAh + 8);
        rAl[0] = *(const uint4*)bAl;  rAl[1] = *(const uint4*)(bAl + 8);
        const __nv_bfloat16* bBh = pWh + (size_t)(col0 + bn) * KP + k0 + bpart * 8;
        const __nv_bfloat16* bBl = pWl + (size_t)(col0 + bn) * KP + k0 + bpart * 8;
        rBh = *(const uint4*)bBh;
        rBl = *(const uint4*)bBl;
    };

    load_tile(0);
    int k0 = 0;
    for (int it = 0; it < KP / 32; ++it) {
        __syncthreads();
        *(uint4*)&sAh[arow][apart * 16]     = rAh[0];
        *(uint4*)&sAh[arow][apart * 16 + 8] = rAh[1];
        *(uint4*)&sAl[arow][apart * 16]     = rAl[0];
        *(uint4*)&sAl[arow][apart * 16 + 8] = rAl[1];
        *(uint4*)&sBh[bn][bpart * 8] = rBh;
        *(uint4*)&sBl[bn][bpart * 8] = rBl;
        __syncthreads();
        if (it + 1 < KP / 32) load_tile(k0 + 32);
        #pragma unroll
        for (int ks = 0; ks < 2; ++ks) {
            const int kb = ks * 16 + q * 2;
            uint32_t afh[2][4], afl[2][4];
            #pragma unroll
            for (int mt = 0; mt < 2; mt++) {
                int r0 = rw * 32 + mt * 16 + gid;
                afh[mt][0] = *(const uint32_t*)&sAh[r0][kb];
                afh[mt][1] = *(const uint32_t*)&sAh[r0 + 8][kb];
                afh[mt][2] = *(const uint32_t*)&sAh[r0][kb + 8];
                afh[mt][3] = *(const uint32_t*)&sAh[r0 + 8][kb + 8];
                afl[mt][0] = *(const uint32_t*)&sAl[r0][kb];
                afl[mt][1] = *(const uint32_t*)&sAl[r0 + 8][kb];
                afl[mt][2] = *(const uint32_t*)&sAl[r0][kb + 8];
                afl[mt][3] = *(const uint32_t*)&sAl[r0 + 8][kb + 8];
            }
            #pragma unroll
            for (int nt = 0; nt < 4; nt++) {
                int nn = cw * 32 + nt * 8 + gid;
                uint32_t bh0 = *(const uint32_t*)&sBh[nn][kb];
                uint32_t bh1 = *(const uint32_t*)&sBh[nn][kb + 8];
                uint32_t bl0 = *(const uint32_t*)&sBl[nn][kb];
                uint32_t bl1 = *(const uint32_t*)&sBl[nn][kb + 8];
                #pragma unroll
                for (int mt = 0; mt < 2; mt++) {
                    MMA_BF16(acc[mt][nt], afh[mt], bh0, bh1);
                    MMA_BF16(acc[mt][nt], afh[mt], bl0, bl1);
                    MMA_BF16(acc[mt][nt], afl[mt], bh0, bh1);
                }
            }
        }
        k0 += 32;
    }

    float tsum[4][2], tmax[4][2];
    #pragma unroll
    for (int nt = 0; nt < 4; nt++)
        #pragma unroll
        for (int p = 0; p < 2; p++) { tsum[nt][p] = 0.f; tmax[nt][p] = -INFINITY; }

    #pragma unroll
    for (int mt = 0; mt < 2; mt++) {
        #pragma unroll
        for (int rp = 0; rp < 2; rp++) {
            int lr = rw * 32 + mt * 16 + gid + rp * 8;
            int xl = lr >> 6, y = lr & 63;
            int x  = x0 + xl;
            float a = adjs[xl][y];
            float wv = smvv[xl][y];
            size_t brow = (size_t)(g * 64 + y) * 64 + x;
            #pragma unroll
            for (int nt = 0; nt < 4; nt++) {
                int c = cw * 32 + nt * 8 + q * 2;
                int h = col0 + c;
                if (h < HH) {
                    size_t ob = brow * HH + h;
                    float2 ibv = *(const float2*)&ib[ob];
                    float v0 = fmaxf(ibv.x + a * maWs[y][c]     - acc[mt][nt][rp * 2 + 0], 0.f) * wv;
                    float v1 = fmaxf(ibv.y + a * maWs[y][c + 1] - acc[mt][nt][rp * 2 + 1], 0.f) * wv;
                    if (STORE) *(float2*)&mbout[ob] = make_float2(v0, v1);
                    if (EMIT) {
                        __nv_bfloat16 h0, l0, h1, l1;
                        split_bf16(v0, h0, l0);
                        split_bf16(v1, h1, l1);
                        size_t pb = brow * KP + h;
                        __nv_bfloat162 hp; hp.x = h0; hp.y = h1;
                        __nv_bfloat162 lp; lp.x = l0; lp.y = l1;
                        *(__nv_bfloat162*)&pOh[pb] = hp;
                        *(__nv_bfloat162*)&pOl[pb] = lp;
                    }
                    tsum[nt][0] += v0;  tmax[nt][0] = fmaxf(tmax[nt][0], v0);
                    tsum[nt][1] += v1;  tmax[nt][1] = fmaxf(tmax[nt][1], v1);
                }
            }
        }
    }
    {
        int slot = rw * 8 + gid;
        #pragma unroll
        for (int nt = 0; nt < 4; nt++) {
            int c = cw * 32 + nt * 8 + q * 2;
            psum[slot][c]     = tsum[nt][0];
            psum[slot][c + 1] = tsum[nt][1];
            pmax[slot][c]     = tmax[nt][0];
            pmax[slot][c + 1] = tmax[nt][1];
        }
    }
    __syncthreads();
    if (tid < 128) {
        int xl = tid >> 6, c = tid & 63;
        if (col0 + c < HH) {
            float s = 0.f, m = -INFINITY;
            #pragma unroll
            for (int r = 0; r < 16; r++) {
                s += psum[xl * 16 + r][c];
                m = fmaxf(m, pmax[xl * 16 + r][c]);
            }
            float aggv = s * (1.f / (1.f + expf(-m)));
            size_t idx = (size_t)(g * 64 + x0 + xl) * HH + col0 + c;
            if (UPDATE) g_msg_atom[idx] += aggv;
            else        g_agg[idx] = aggv;
        }
    }
}

// ---------------------------------------------------------------------------
// input_atom = relu(f_atoms @ W_i_atom) (also -> msg_atom)
// ---------------------------------------------------------------------------
__global__ void k_input_atom(const float* __restrict__ A, const float* __restrict__ W) {
    const int row0 = blockIdx.y * 64;
    const int col0 = blockIdx.x * 64;
    __shared__ float As[16][68];
    __shared__ float Bs[16][68];
    const int tid = threadIdx.x;
    const int tx = tid & 15, ty = tid >> 4;
    float acc[4][4] = {};
    for (int k0 = 0; k0 < AF; k0 += 16) {
        __syncthreads();
        {
            int kk = tid & 15;
            int k  = k0 + kk;
            #pragma unroll
            for (int qq = 0; qq < 4; qq++) {
                int r = (tid >> 4) + qq * 16;
                As[kk][r] = (k < AF) ? A[(row0 + r) * AF + k] : 0.f;
            }
        }
        {
            int nn = tid & 63;
            int c  = col0 + nn;
            #pragma unroll
            for (int qq = 0; qq < 4; qq++) {
                int kk = (tid >> 6) + qq * 4;
                int k  = k0 + kk;
                Bs[kk][nn] = (k < AF && c < HH) ? W[k * HH + c] : 0.f;
            }
        }
        __syncthreads();
        #pragma unroll
        for (int kk = 0; kk < 16; kk++) {
            float4 a4 = *(const float4*)&As[kk][ty * 4];
            float4 b4 = *(const float4*)&Bs[kk][tx * 4];
            float a[4] = {a4.x, a4.y, a4.z, a4.w};
            float b[4] = {b4.x, b4.y, b4.z, b4.w};
            #pragma unroll
            for (int i = 0; i < 4; i++)
                #pragma unroll
                for (int j = 0; j < 4; j++)
                    acc[i][j] += a[i] * b[j];
        }
    }
    #pragma unroll
    for (int i = 0; i < 4; i++) {
        int r = row0 + ty * 4 + i;
        #pragma unroll
        for (int j = 0; j < 4; j++) {
            int c = col0 + tx * 4 + j;
            if (c < HH) {
                float v = acc[i][j];
                v = v > 0.f ? v : 0.f;
                g_input_atom[r * HH + c] = v;
                g_msg_atom[r * HH + c]   = v;
            }
        }
    }
}

// ---------------------------------------------------------------------------
// agg over input_bond with adjacency skip (values >= 0, zero rows contribute 0)
// ---------------------------------------------------------------------------
__global__ void k_agg(const float* __restrict__ mb, const float* __restrict__ adj) {
    int gm = blockIdx.x;
    int g = gm >> 6, m = gm & 63;
    __shared__ float adjc[64];
    int tid = threadIdx.x;
    if (tid < 64) adjc[tid] = adj[(size_t)(g * 64 + tid) * 64 + m];
    __syncthreads();
    int h = tid;
    if (h >= HH) return;
    const float* base = mb + ((size_t)(g * 64) * 64 + m) * HH + h;
    float s = 0.f, mx = 0.f;   // zero rows contribute value 0 (relu >= 0)
    for (int n = 0; n < 64; n++) {
        if (adjc[n] != 0.f) {
            float v = base[(size_t)n * 64 * HH];
            s += v;
            mx = fmaxf(mx, v);
        }
    }
    float a = s * (1.f / (1.f + expf(-mx)));
    g_msg_atom[gm * HH + h] += a;
}

// ---------------------------------------------------------------------------
__global__ void k_resonance2(const float* __restrict__ adj) {
    int g = blockIdx.x;
    __shared__ float mt[64][101];
    __shared__ float rr[64][65];
    int tid = threadIdx.x;
    int tx = tid & 15, ty = tid >> 4;
    float acc[4][4] = {};
    for (int c = 0; c < 3; ++c) {
        __syncthreads();
        for (int l = tid; l < 6400; l += 256) {
            int r = l / 100, k = l - r * 100;
            mt[r][k] = g_msg_atom[((size_t)(g * 64 + r)) * 300 + c * 100 + k];
        }
        __syncthreads();
        for (int kk = 0; kk < 100; ++kk) {
            float a[4], b[4];
            #pragma unroll
            for (int i = 0; i < 4; i++) a[i] = mt[ty * 4 + i][kk];
            #pragma unroll
            for (int j = 0; j < 4; j++) b[j] = mt[tx * 4 + j][kk];
            #pragma unroll
            for (int i = 0; i < 4; i++)
                #pragma unroll
                for (int j = 0; j < 4; j++)
                    acc[i][j] += a[i] * b[j];
        }
    }
    #pragma unroll
    for (int i = 0; i < 4; i++)
        #pragma unroll
        for (int j = 0; j < 4; j++)
            rr[ty * 4 + i][tx * 4 + j] = acc[i][j];
    __syncthreads();
    if (tid < 64) {
        int m = tid;
        float mxv = -INFINITY;
        for (int n = 0; n < 64; n++) {
            float v = rr[n][m] * adj[((size_t)(g * 64 + n)) * 64 + m];
            rr[n][m] = v;
            mxv = fmaxf(mxv, v);
        }
        float sum = 0.f;
        for (int n = 0; n < 64; n++) {
            float e = expf(rr[n][m] - mxv);
            rr[n][m] = e;
            sum += e;
        }
        float inv = 1.f / sum;
        for (int n = 0; n < 64; n++)
            g_sm[(size_t)(g * 64 + n) * 64 + m] = rr[n][m] * inv;
    }
}

// ---------------------------------------------------------------------------
__global__ void k_output(const float* __restrict__ W, const float* __restrict__ bias,
                         float* __restrict__ out) {
    const int row0 = blockIdx.y * 64;
    const int col0 = blockIdx.x * 64;
    __shared__ float As[16][68];
    __shared__ float Bs[16][68];
    const int tid = threadIdx.x;
    const int tx = tid & 15, ty = tid >> 4;
    float acc[4][4] = {};
    for (int k0 = 0; k0 < 900; k0 += 16) {
        __syncthreads();
        {
            int kk = tid & 15;
            int k  = k0 + kk;
            #pragma unroll
            for (int qq = 0; qq < 4; qq++) {
                int r = (tid >> 4) + qq * 16;
                int row = row0 + r;
                float v = 0.f;
                if (k < 900) {
                    if (k < 300)       v = g_agg[row * HH + k];
                    else if (k < 600)  v = g_msg_atom[row * HH + (k - 300)];
                    else               v = g_input_atom[row * HH + (k - 600)];
                }
                As[kk][r] = v;
            }
        }
        {
            int nn = tid & 63;
            int c  = col0 + nn;
            #pragma unroll
            for (int qq = 0; qq < 4; qq++) {
                int kk = (tid >> 6) + qq * 4;
                int k  = k0 + kk;
                Bs[kk][nn] = (k < 900 && c < HH) ? W[k * HH + c] : 0.f;
            }
        }
        __syncthreads();
        #pragma unroll
        for (int kk = 0; kk < 16; kk++) {
            float4 a4 = *(const float4*)&As[kk][ty * 4];
            float4 b4 = *(const float4*)&Bs[kk][tx * 4];
            float a[4] = {a4.x, a4.y, a4.z, a4.w};
            float b[4] = {b4.x, b4.y, b4.z, b4.w};
            #pragma unroll
            for (int i = 0; i < 4; i++)
                #pragma unroll
                for (int j = 0; j < 4; j++)
                    acc[i][j] += a[i] * b[j];
        }
    }
    #pragma unroll
    for (int i = 0; i < 4; i++) {
        int r = row0 + ty * 4 + i;
        #pragma unroll
        for (int j = 0; j < 4; j++) {
            int c = col0 + tx * 4 + j;
            if (c < HH) {
                float v = acc[i][j] + bias[c];
                out[r * HH + c] = v > 0.f ? v : 0.f;
            }
        }
    }
}

// ---------------------------------------------------------------------------
extern "C" void kernel_launch(void* const* d_in, const int* in_sizes, int n_in,
                              void* d_out, int out_size) {
    const float* f_atoms  = (const float*)d_in[0];
    const float* f_bonds  = (const float*)d_in[1];
    const float* adj      = (const float*)d_in[2];
    const float* W_i_atom = (const float*)d_in[3];
    const float* W_i_bond = (const float*)d_in[4];
    const float* W_h0     = (const float*)d_in[5];
    const float* W_h1     = (const float*)d_in[6];
    const float* W_o      = (const float*)d_in[7];
    const float* b_o      = (const float*)d_in[8];
    float* out = (float*)d_out;

    float *p_inbond = 0, *p_mbB = 0, *p_msg = 0, *p_maW = 0;
    __nv_bfloat16 *p0h = 0, *p0l = 0, *p1h = 0, *p1l = 0;
    __nv_bfloat16 *wt0h = 0, *wt0l = 0, *wt1h = 0, *wt1l = 0;
    cudaGetSymbolAddress((void**)&p_inbond, g_input_bond);
    cudaGetSymbolAddress((void**)&p_mbB, g_mbB);
    cudaGetSymbolAddress((void**)&p_msg, g_msg_atom);
    cudaGetSymbolAddress((void**)&p_maW, g_maW);
    cudaGetSymbolAddress((void**)&p0h, g_P0h);
    cudaGetSymbolAddress((void**)&p0l, g_P0l);
    cudaGetSymbolAddress((void**)&p1h, g_P1h);
    cudaGetSymbolAddress((void**)&p1l, g_P1l);
    cudaGetSymbolAddress((void**)&wt0h, g_Wt0h);
    cudaGetSymbolAddress((void**)&wt0l, g_Wt0l);
    cudaGetSymbolAddress((void**)&wt1h, g_Wt1h);
    cudaGetSymbolAddress((void**)&wt1l, g_Wt1l);

    float* mb_final = (out_size >= AR * HH + BR * HH) ? (out + AR * HH) : p_mbB;

    const int SMEM_MMA = 66560;
    cudaFuncSetAttribute(k_bondstep_mma<1, 1, 0>,
                         cudaFuncAttributeMaxDynamicSharedMemorySize, SMEM_MMA);
    cudaFuncSetAttribute(k_bondstep_mma<0, 0, 1>,
                         cudaFuncAttributeMaxDynamicSharedMemorySize, SMEM_MMA);

    // sparsity compaction (adj binary, ~30% dense)
    k_reset<<<1, 32>>>();
    k_compact<<<(BR + 255) / 256, 256>>>(adj);

    k_input_atom<<<dim3(5, 32), 256>>>(f_atoms, W_i_atom);
    k_convW<<<HH, KP>>>(W_h0, wt0h, wt0l);
    k_convW<<<HH, KP>>>(W_h1, wt1h, wt1l);
    // input_bond over nonzero rows only (fp32 + bf16 planes P0)
    k_inbond_idx<<<dim3(5, BR / 128), 128>>>(f_bonds, W_i_bond, p_inbond, p0h, p0l);

    // ---- depth step 0 (prev = input_bond) ----
    k_agg<<<2048, 320>>>(p_inbond, adj);
    k_resonance2<<<32, 256>>>(adj);
    k_gemm_f2<HH><<<dim3(5, AR / 128), 128>>>(p_msg, W_h0, p_maW, HH);
    k_bondstep_mma<1, 1, 0><<<dim3(5, BR / 128), 256, SMEM_MMA>>>(
        p0h, p0l, wt0h, wt0l, p_inbond, p_maW, adj, mb_final, p1h, p1l);

    // ---- depth step 1 (prev = mbA planes) ----
    k_resonance2<<<32, 256>>>(adj);
    k_gemm_f2<HH><<<dim3(5, AR / 128), 128>>>(p_msg, W_h1, p_maW, HH);
    k_bondstep_mma<0, 0, 1><<<dim3(5, BR / 128), 256, SMEM_MMA>>>(
        p1h, p1l, wt1h, wt1l, p_inbond, p_maW, adj, mb_final, nullptr, nullptr);

    // ---- readout ----
    k_output<<<dim3(5, 32), 256>>>(W_o, b_o, out);
}

// round 8
// speedup vs baseline: 3.0783x; 1.0217x over previous
#include <cuda_runtime.h>
#include <cuda_bf16.h>
#include <math.h>
#include <stdint.h>

// Problem constants
#define GG 32
#define NA 64
#define HH 300
#define AF 133
#define BF 147
#define AR (GG*NA)     // 2048
#define BR (GG*NA*NA)  // 131072
#define KP 320         // padded K for bf16 planes (zero pads via zero-init)

// Scratch (zero-initialized device globals; allocation-free)
__device__ float g_input_atom[AR*HH];
__device__ float g_msg_atom[AR*HH];
__device__ float g_agg[AR*HH];
__device__ float g_maW[AR*HH];
__device__ float g_input_bond[BR*HH];   // 157 MB fp32 (zero rows stay zero-init)
__device__ float g_mbB[BR*HH];          // fallback mb_final
__device__ float g_sm[BR];
__device__ int   g_cnt;
__device__ int   g_rows[BR];
// bf16 hi/lo planes (pads + zero rows never written -> stay zero)
__device__ __nv_bfloat16 g_P0h[(size_t)BR*KP];
__device__ __nv_bfloat16 g_P0l[(size_t)BR*KP];
__device__ __nv_bfloat16 g_P1h[(size_t)BR*KP];
__device__ __nv_bfloat16 g_P1l[(size_t)BR*KP];
__device__ __nv_bfloat16 g_Wt0h[KP*KP];
__device__ __nv_bfloat16 g_Wt0l[KP*KP];
__device__ __nv_bfloat16 g_Wt1h[KP*KP];
__device__ __nv_bfloat16 g_Wt1l[KP*KP];

// ---------------------------------------------------------------------------
// f32x2 helpers
// ---------------------------------------------------------------------------
__device__ __forceinline__ unsigned long long pack2(float x, float y) {
    unsigned long long r;
    asm("mov.b64 %0, {%1, %2};" : "=l"(r)
        : "r"(__float_as_uint(x)), "r"(__float_as_uint(y)));
    return r;
}
__device__ __forceinline__ void ffma2(unsigned long long& d, unsigned long long a,
                                      unsigned long long b) {
    asm("fma.rn.f32x2 %0, %1, %2, %3;" : "=l"(d) : "l"(a), "l"(b), "l"(d));
}
__device__ __forceinline__ float2 unpack2(unsigned long long v) {
    unsigned lo, hi;
    asm("mov.b64 {%0, %1}, %2;" : "=r"(lo), "=r"(hi) : "l"(v));
    return make_float2(__uint_as_float(lo), __uint_as_float(hi));
}

#define MMA_BF16(c, a, b0, b1) \
    asm volatile("mma.sync.aligned.m16n8k16.row.col.f32.bf16.bf16.f32 " \
                 "{%0,%1,%2,%3}, {%4,%5,%6,%7}, {%8,%9}, {%0,%1,%2,%3};" \
                 : "+f"((c)[0]), "+f"((c)[1]), "+f"((c)[2]), "+f"((c)[3]) \
                 : "r"((a)[0]), "r"((a)[1]), "r"((a)[2]), "r"((a)[3]), \
                   "r"(b0), "r"(b1))

#define LDSM_X4(R, A) \
    asm volatile("ldmatrix.sync.aligned.m8n8.x4.shared.b16 {%0,%1,%2,%3}, [%4];" \
                 : "=r"((R)[0]), "=r"((R)[1]), "=r"((R)[2]), "=r"((R)[3]) : "r"(A))

__device__ __forceinline__ uint32_t lds_addr(const void* p) {
    return (uint32_t)__cvta_generic_to_shared(p);
}

__device__ __forceinline__ void split_bf16(float v, __nv_bfloat16& h, __nv_bfloat16& l) {
    h = __float2bfloat16(v);
    l = __float2bfloat16(v - __bfloat162float(h));
}

// ---------------------------------------------------------------------------
// Sparse row compaction (adj is binary; ~30% density)
// ---------------------------------------------------------------------------
__global__ void k_reset() { if (threadIdx.x == 0) g_cnt = 0; }

__global__ void k_compact(const float* __restrict__ adj) {
    int i = blockIdx.x * 256 + threadIdx.x;
    if (i < BR && adj[i] != 0.f) {
        int idx = atomicAdd(&g_cnt, 1);
        g_rows[idx] = i;
    }
}

// ---------------------------------------------------------------------------
// Indexed input_bond GEMM over compacted rows only
// ---------------------------------------------------------------------------
#define BKg 12
__global__ __launch_bounds__(128, 3)
void k_inbond_idx(const float* __restrict__ A, const float* __restrict__ W,
                  float* __restrict__ Co,
                  __nv_bfloat16* __restrict__ pH, __nv_bfloat16* __restrict__ pL) {
    const int cnt = g_cnt;
    const int row0 = blockIdx.y * 128;
    if (row0 >= cnt) return;
    const int col0 = blockIdx.x * 64;
    __shared__ __align__(16) float As[BKg][132];
    __shared__ __align__(16) float Bs[BKg][72];
    const int tid = threadIdx.x;
    const int rg = tid >> 3;
    const int cg = tid & 7;

    int ar[3], ac4[3], ridx[3];
    #pragma unroll
    for (int q = 0; q < 3; q++) {
        int l = q * 128 + tid;
        ar[q]  = l / 3;
        ac4[q] = l - ar[q] * 3;
        int slot = row0 + ar[q];
        ridx[q] = (slot < cnt) ? g_rows[slot] : -1;
    }

    const int bk0  = tid >> 4;
    const int bk1  = (tid + 128) >> 4;
    const int bc4  = tid & 15;
    const bool hasB1  = (tid < 64);
    const bool bcolOK = (col0 + 4 * bc4 + 4 <= HH);

    unsigned long long acc[8][4];
    #pragma unroll
    for (int i = 0; i < 8; i++)
        #pragma unroll
        for (int p = 0; p < 4; p++) acc[i][p] = 0ull;

    float4 ra[3], rb0, rb1;
    auto load_tile = [&](int k0) {
        #pragma unroll
        for (int q = 0; q < 3; q++) {
            int gk = k0 + 4 * ac4[q];
            float v[4] = {0.f, 0.f, 0.f, 0.f};
            if (ridx[q] >= 0) {
                const float* ap = &A[(size_t)ridx[q] * BF + gk];
                #pragma unroll
                for (int e = 0; e < 4; e++) if (gk + e < BF) v[e] = ap[e];
            }
            ra[q] = make_float4(v[0], v[1], v[2], v[3]);
        }
        {
            int gk = k0 + bk0;
            if (gk < BF && bcolOK)
                rb0 = *(const float4*)&W[(size_t)gk * HH + col0 + 4 * bc4];
            else rb0 = make_float4(0.f, 0.f, 0.f, 0.f);
        }
        if (hasB1) {
            int gk = k0 + bk1;
            if (gk < BF && bcolOK)
                rb1 = *(const float4*)&W[(size_t)gk * HH + col0 + 4 * bc4];
            else rb1 = make_float4(0.f, 0.f, 0.f, 0.f);
        }
    };

    const int nIter = (BF + BKg - 1) / BKg;
    load_tile(0);
    int k0 = 0;
    for (int it = 0; it < nIter; ++it) {
        __syncthreads();
        #pragma unroll
        for (int q = 0; q < 3; q++) {
            int kb = 4 * ac4[q];
            As[kb + 0][ar[q]] = ra[q].x;
            As[kb + 1][ar[q]] = ra[q].y;
            As[kb + 2][ar[q]] = ra[q].z;
            As[kb + 3][ar[q]] = ra[q].w;
        }
        *(float4*)&Bs[bk0][4 * bc4] = rb0;
        if (hasB1) *(float4*)&Bs[bk1][4 * bc4] = rb1;
        __syncthreads();
        if (it + 1 < nIter) load_tile(k0 + BKg);
        #pragma unroll
        for (int kk = 0; kk < BKg; ++kk) {
            float4 a0 = *(const float4*)&As[kk][rg * 8];
            float4 a1 = *(const float4*)&As[kk][rg * 8 + 4];
            ulonglong2 b01 = *(const ulonglong2*)&Bs[kk][cg * 8];
            ulonglong2 b23 = *(const ulonglong2*)&Bs[kk][cg * 8 + 4];
            float av[8] = {a0.x, a0.y, a0.z, a0.w, a1.x, a1.y, a1.z, a1.w};
            #pragma unroll
            for (int i = 0; i < 8; i++) {
                unsigned long long ap = pack2(av[i], av[i]);
                ffma2(acc[i][0], ap, b01.x);
                ffma2(acc[i][1], ap, b01.y);
                ffma2(acc[i][2], ap, b23.x);
                ffma2(acc[i][3], ap, b23.y);
            }
        }
        k0 += BKg;
    }

    const bool fastcol = (col0 + 64 <= HH);
    #pragma unroll
    for (int i = 0; i < 8; i++) {
        int slot = row0 + rg * 8 + i;
        if (slot >= cnt) continue;
        size_t row = g_rows[slot];
        float v[8];
        #pragma unroll
        for (int p = 0; p < 4; p++) {
            float2 f = unpack2(acc[i][p]);
            v[2 * p] = f.x; v[2 * p + 1] = f.y;
        }
        #pragma unroll
        for (int jj = 0; jj < 8; jj++) v[jj] = fmaxf(v[jj], 0.f);
        size_t base = row * HH + col0 + cg * 8;
        if (fastcol) {
            *(float4*)&Co[base]     = make_float4(v[0], v[1], v[2], v[3]);
            *(float4*)&Co[base + 4] = make_float4(v[4], v[5], v[6], v[7]);
            __align__(16) __nv_bfloat16 hb[8], lb[8];
            #pragma unroll
            for (int jj = 0; jj < 8; jj++) split_bf16(v[jj], hb[jj], lb[jj]);
            size_t pb = row * KP + col0 + cg * 8;
            *(uint4*)&pH[pb] = *(uint4*)hb;
            *(uint4*)&pL[pb] = *(uint4*)lb;
        } else {
            #pragma unroll
            for (int jj = 0; jj < 8; jj++) {
                int c = col0 + cg * 8 + jj;
                if (c < HH) {
                    Co[base + jj] = v[jj];
                    __nv_bfloat16 hb, lb;
                    split_bf16(v[jj], hb, lb);
                    pH[row * KP + c] = hb;
                    pL[row * KP + c] = lb;
                }
            }
        }
    }
}

// ---------------------------------------------------------------------------
// f32x2 SGEMM (maW only): C = A @ W
// ---------------------------------------------------------------------------
template<int K>
__global__ __launch_bounds__(128, 3)
void k_gemm_f2(const float* __restrict__ A, const float* __restrict__ W,
               float* __restrict__ Co, int N) {
    const int row0 = blockIdx.y * 128;
    const int col0 = blockIdx.x * 64;
    __shared__ __align__(16) float As[BKg][132];
    __shared__ __align__(16) float Bs[BKg][72];
    const int tid = threadIdx.x;
    const int rg = tid >> 3;
    const int cg = tid & 7;

    int ar[3], ac4[3];
    #pragma unroll
    for (int q = 0; q < 3; q++) {
        int l = q * 128 + tid;
        ar[q]  = l / 3;
        ac4[q] = l - ar[q] * 3;
    }
    const int bk0  = tid >> 4;
    const int bk1  = (tid + 128) >> 4;
    const int bc4  = tid & 15;
    const bool hasB1  = (tid < 64);
    const bool bcolOK = (col0 + 4 * bc4 + 4 <= N);

    unsigned long long acc[8][4];
    #pragma unroll
    for (int i = 0; i < 8; i++)
        #pragma unroll
        for (int p = 0; p < 4; p++) acc[i][p] = 0ull;

    float4 ra[3], rb0, rb1;
    auto load_tile = [&](int k0) {
        #pragma unroll
        for (int q = 0; q < 3; q++)
            ra[q] = *(const float4*)&A[(size_t)(row0 + ar[q]) * K + k0 + 4 * ac4[q]];
        {
            int gk = k0 + bk0;
            rb0 = (gk < K && bcolOK) ? *(const float4*)&W[(size_t)gk * N + col0 + 4 * bc4]
                                     : make_float4(0.f, 0.f, 0.f, 0.f);
        }
        if (hasB1) {
            int gk = k0 + bk1;
            rb1 = (gk < K && bcolOK) ? *(const float4*)&W[(size_t)gk * N + col0 + 4 * bc4]
                                     : make_float4(0.f, 0.f, 0.f, 0.f);
        }
    };

    const int nIter = (K + BKg - 1) / BKg;
    load_tile(0);
    int k0 = 0;
    for (int it = 0; it < nIter; ++it) {
        __syncthreads();
        #pragma unroll
        for (int q = 0; q < 3; q++) {
            int kb = 4 * ac4[q];
            As[kb + 0][ar[q]] = ra[q].x;
            As[kb + 1][ar[q]] = ra[q].y;
            As[kb + 2][ar[q]] = ra[q].z;
            As[kb + 3][ar[q]] = ra[q].w;
        }
        *(float4*)&Bs[bk0][4 * bc4] = rb0;
        if (hasB1) *(float4*)&Bs[bk1][4 * bc4] = rb1;
        __syncthreads();
        if (it + 1 < nIter) load_tile(k0 + BKg);
        #pragma unroll
        for (int kk = 0; kk < BKg; ++kk) {
            float4 a0 = *(const float4*)&As[kk][rg * 8];
            float4 a1 = *(const float4*)&As[kk][rg * 8 + 4];
            ulonglong2 b01 = *(const ulonglong2*)&Bs[kk][cg * 8];
            ulonglong2 b23 = *(const ulonglong2*)&Bs[kk][cg * 8 + 4];
            float av[8] = {a0.x, a0.y, a0.z, a0.w, a1.x, a1.y, a1.z, a1.w};
            #pragma unroll
            for (int i = 0; i < 8; i++) {
                unsigned long long ap = pack2(av[i], av[i]);
                ffma2(acc[i][0], ap, b01.x);
                ffma2(acc[i][1], ap, b01.y);
                ffma2(acc[i][2], ap, b23.x);
                ffma2(acc[i][3], ap, b23.y);
            }
        }
        k0 += BKg;
    }

    const bool fastcol = (col0 + 64 <= N);
    #pragma unroll
    for (int i = 0; i < 8; i++) {
        size_t row = row0 + rg * 8 + i;
        float v[8];
        #pragma unroll
        for (int p = 0; p < 4; p++) {
            float2 f = unpack2(acc[i][p]);
            v[2 * p] = f.x; v[2 * p + 1] = f.y;
        }
        size_t base = row * N + col0 + cg * 8;
        if (fastcol) {
            *(float4*)&Co[base]     = make_float4(v[0], v[1], v[2], v[3]);
            *(float4*)&Co[base + 4] = make_float4(v[4], v[5], v[6], v[7]);
        } else {
            #pragma unroll
            for (int jj = 0; jj < 8; jj++)
                if (col0 + cg * 8 + jj < N) Co[base + jj] = v[jj];
        }
    }
}

// ---------------------------------------------------------------------------
// W transpose + split
// ---------------------------------------------------------------------------
__global__ void k_convW(const float* __restrict__ W,
                        __nv_bfloat16* __restrict__ hi, __nv_bfloat16* __restrict__ lo) {
    int n = blockIdx.x;
    int k = threadIdx.x;
    if (k < HH) {
        float v = W[(size_t)k * HH + n];
        __nv_bfloat16 h, l;
        split_bf16(v, h, l);
        hi[(size_t)n * KP + k] = h;
        lo[(size_t)n * KP + k] = l;
    }
}

// ---------------------------------------------------------------------------
// Tensor-core fused bond step — ldmatrix fragment loads (round-8 change)
// ---------------------------------------------------------------------------
template<int UPDATE, int EMIT, int STORE>
__global__ __launch_bounds__(256)
void k_bondstep_mma(const __nv_bfloat16* __restrict__ pAh, const __nv_bfloat16* __restrict__ pAl,
                    const __nv_bfloat16* __restrict__ pWh, const __nv_bfloat16* __restrict__ pWl,
                    const float* __restrict__ ib, const float* __restrict__ maW,
                    const float* __restrict__ adj, float* __restrict__ mbout,
                    __nv_bfloat16* __restrict__ pOh, __nv_bfloat16* __restrict__ pOl) {
    extern __shared__ __align__(16) char smraw[];
    __nv_bfloat16 (*sAh)[40] = (__nv_bfloat16(*)[40])(smraw + 0);
    __nv_bfloat16 (*sAl)[40] = (__nv_bfloat16(*)[40])(smraw + 10240);
    __nv_bfloat16 (*sBh)[40] = (__nv_bfloat16(*)[40])(smraw + 20480);
    __nv_bfloat16 (*sBl)[40] = (__nv_bfloat16(*)[40])(smraw + 25600);
    float (*maWs)[68]        = (float(*)[68])(smraw + 30720);
    float (*psum)[65]        = (float(*)[65])(smraw + 48128);
    float (*pmax)[65]        = (float(*)[65])(smraw + 56448);
    float (*adjs)[64]        = (float(*)[64])(smraw + 64768);
    float (*smvv)[64]        = (float(*)[64])(smraw + 65280);

    const int row0 = blockIdx.y * 128;
    const int col0 = blockIdx.x * 64;
    const int g  = row0 >> 12;
    const int x0 = (row0 >> 6) & 63;
    const int tid = threadIdx.x;
    const int w   = tid >> 5;
    const int rw  = w & 3;
    const int cw  = w >> 2;
    const int lane = tid & 31;
    const int gid = lane >> 2;
    const int q   = lane & 3;

    if (tid < 128) {
        int xl = tid >> 6, y = tid & 63;
        adjs[xl][y] = adj[(size_t)(g * 64 + x0 + xl) * 64 + y];
        smvv[xl][y] = g_sm[(size_t)(g * 64 + y) * 64 + x0 + xl];
    }
    for (int l = tid; l < 64 * 16; l += 256) {
        int y = l >> 4, c4 = (l & 15) * 4;
        int c = col0 + c4;
        float4 v;
        if (c + 4 <= HH) v = *(const float4*)&maW[(size_t)(g * 64 + y) * HH + c];
        else {
            float t[4];
            #pragma unroll
            for (int e = 0; e < 4; e++)
                t[e] = (c + e < HH) ? maW[(size_t)(g * 64 + y) * HH + c + e] : 0.f;
            v = make_float4(t[0], t[1], t[2], t[3]);
        }
        *(float4*)&maWs[y][c4] = v;
    }

    const int arow  = tid >> 1, apart = tid & 1;
    const int bn    = tid >> 2, bpart = tid & 3;

    // ldmatrix lane->address geometry (row stride = 40 bf16 = 80 B)
    const int aR = rw * 32 + (lane & 15);            // A row (mt=0)
    const int aC = (lane >> 4) * 8;                  // k offset 0/8
    const uint32_t addrAh = lds_addr(&sAh[aR][aC]);
    const uint32_t addrAl = lds_addr(&sAl[aR][aC]);
    const int bR = cw * 32 + ((lane >> 4) & 1) * 8 + (lane & 7);  // B n-row (p=0)
    const int bC = ((lane >> 3) & 1) * 8;                          // k offset 0/8
    const uint32_t addrBh = lds_addr(&sBh[bR][bC]);
    const uint32_t addrBl = lds_addr(&sBl[bR][bC]);

    float acc[2][4][4];
    #pragma unroll
    for (int mt = 0; mt < 2; mt++)
        #pragma unroll
        for (int nt = 0; nt < 4; nt++)
            #pragma unroll
            for (int e = 0; e < 4; e++) acc[mt][nt][e] = 0.f;

    uint4 rAh[2], rAl[2], rBh, rBl;
    auto load_tile = [&](int k0) {
        const __nv_bfloat16* bAh = pAh + (size_t)(row0 + arow) * KP + k0 + apart * 16;
        const __nv_bfloat16* bAl = pAl + (size_t)(row0 + arow) * KP + k0 + apart * 16;
        rAh[0] = *(const uint4*)bAh;  rAh[1] = *(const uint4*)(bAh + 8);
        rAl[0] = *(const uint4*)bAl;  rAl[1] = *(const uint4*)(bAl + 8);
        const __nv_bfloat16* bBh = pWh + (size_t)(col0 + bn) * KP + k0 + bpart * 8;
        const __nv_bfloat16* bBl = pWl + (size_t)(col0 + bn) * KP + k0 + bpart * 8;
        rBh = *(const uint4*)bBh;
        rBl = *(const uint4*)bBl;
    };

    load_tile(0);
    int k0 = 0;
    for (int it = 0; it < KP / 32; ++it) {
        __syncthreads();
        *(uint4*)&sAh[arow][apart * 16]     = rAh[0];
        *(uint4*)&sAh[arow][apart * 16 + 8] = rAh[1];
        *(uint4*)&sAl[arow][apart * 16]     = rAl[0];
        *(uint4*)&sAl[arow][apart * 16 + 8] = rAl[1];
        *(uint4*)&sBh[bn][bpart * 8] = rBh;
        *(uint4*)&sBl[bn][bpart * 8] = rBl;
        __syncthreads();
        if (it + 1 < KP / 32) load_tile(k0 + 32);
        #pragma unroll
        for (int ks = 0; ks < 2; ++ks) {
            const uint32_t ko = ks * 32;     // 16 bf16 = 32 bytes
            uint32_t afh[2][4], afl[2][4], bfh[2][4], bfl[2][4];
            #pragma unroll
            for (int mt = 0; mt < 2; mt++) {
                LDSM_X4(afh[mt], addrAh + mt * 1280 + ko);
                LDSM_X4(afl[mt], addrAl + mt * 1280 + ko);
            }
            #pragma unroll
            for (int p = 0; p < 2; p++) {
                LDSM_X4(bfh[p], addrBh + p * 1280 + ko);
                LDSM_X4(bfl[p], addrBl + p * 1280 + ko);
            }
            #pragma unroll
            for (int p = 0; p < 2; p++)
                #pragma unroll
                for (int s = 0; s < 2; s++) {
                    const int nt = 2 * p + s;
                    #pragma unroll
                    for (int mt = 0; mt < 2; mt++) {
                        MMA_BF16(acc[mt][nt], afh[mt], bfh[p][2 * s], bfh[p][2 * s + 1]);
                        MMA_BF16(acc[mt][nt], afh[mt], bfl[p][2 * s], bfl[p][2 * s + 1]);
                        MMA_BF16(acc[mt][nt], afl[mt], bfh[p][2 * s], bfh[p][2 * s + 1]);
                    }
                }
        }
        k0 += 32;
    }

    float tsum[4][2], tmax[4][2];
    #pragma unroll
    for (int nt = 0; nt < 4; nt++)
        #pragma unroll
        for (int p = 0; p < 2; p++) { tsum[nt][p] = 0.f; tmax[nt][p] = -INFINITY; }

    #pragma unroll
    for (int mt = 0; mt < 2; mt++) {
        #pragma unroll
        for (int rp = 0; rp < 2; rp++) {
            int lr = rw * 32 + mt * 16 + gid + rp * 8;
            int xl = lr >> 6, y = lr & 63;
            int x  = x0 + xl;
            float a = adjs[xl][y];
            float wv = smvv[xl][y];
            size_t brow = (size_t)(g * 64 + y) * 64 + x;
            #pragma unroll
            for (int nt = 0; nt < 4; nt++) {
                int c = cw * 32 + nt * 8 + q * 2;
                int h = col0 + c;
                if (h < HH) {
                    size_t ob = brow * HH + h;
                    float2 ibv = *(const float2*)&ib[ob];
                    float v0 = fmaxf(ibv.x + a * maWs[y][c]     - acc[mt][nt][rp * 2 + 0], 0.f) * wv;
                    float v1 = fmaxf(ibv.y + a * maWs[y][c + 1] - acc[mt][nt][rp * 2 + 1], 0.f) * wv;
                    if (STORE) *(float2*)&mbout[ob] = make_float2(v0, v1);
                    if (EMIT) {
                        __nv_bfloat16 h0, l0, h1, l1;
                        split_bf16(v0, h0, l0);
                        split_bf16(v1, h1, l1);
                        size_t pb = brow * KP + h;
                        __nv_bfloat162 hp; hp.x = h0; hp.y = h1;
                        __nv_bfloat162 lp; lp.x = l0; lp.y = l1;
                        *(__nv_bfloat162*)&pOh[pb] = hp;
                        *(__nv_bfloat162*)&pOl[pb] = lp;
                    }
                    tsum[nt][0] += v0;  tmax[nt][0] = fmaxf(tmax[nt][0], v0);
                    tsum[nt][1] += v1;  tmax[nt][1] = fmaxf(tmax[nt][1], v1);
                }
            }
        }
    }
    {
        int slot = rw * 8 + gid;
        #pragma unroll
        for (int nt = 0; nt < 4; nt++) {
            int c = cw * 32 + nt * 8 + q * 2;
            psum[slot][c]     = tsum[nt][0];
            psum[slot][c + 1] = tsum[nt][1];
            pmax[slot][c]     = tmax[nt][0];
            pmax[slot][c + 1] = tmax[nt][1];
        }
    }
    __syncthreads();
    if (tid < 128) {
        int xl = tid >> 6, c = tid & 63;
        if (col0 + c < HH) {
            float s = 0.f, m = -INFINITY;
            #pragma unroll
            for (int r = 0; r < 16; r++) {
                s += psum[xl * 16 + r][c];
                m = fmaxf(m, pmax[xl * 16 + r][c]);
            }
            float aggv = s * (1.f / (1.f + expf(-m)));
            size_t idx = (size_t)(g * 64 + x0 + xl) * HH + col0 + c;
            if (UPDATE) g_msg_atom[idx] += aggv;
            else        g_agg[idx] = aggv;
        }
    }
}

// ---------------------------------------------------------------------------
// input_atom = relu(f_atoms @ W_i_atom) (also -> msg_atom)
// ---------------------------------------------------------------------------
__global__ void k_input_atom(const float* __restrict__ A, const float* __restrict__ W) {
    const int row0 = blockIdx.y * 64;
    const int col0 = blockIdx.x * 64;
    __shared__ float As[16][68];
    __shared__ float Bs[16][68];
    const int tid = threadIdx.x;
    const int tx = tid & 15, ty = tid >> 4;
    float acc[4][4] = {};
    for (int k0 = 0; k0 < AF; k0 += 16) {
        __syncthreads();
        {
            int kk = tid & 15;
            int k  = k0 + kk;
            #pragma unroll
            for (int qq = 0; qq < 4; qq++) {
                int r = (tid >> 4) + qq * 16;
                As[kk][r] = (k < AF) ? A[(row0 + r) * AF + k] : 0.f;
            }
        }
        {
            int nn = tid & 63;
            int c  = col0 + nn;
            #pragma unroll
            for (int qq = 0; qq < 4; qq++) {
                int kk = (tid >> 6) + qq * 4;
                int k  = k0 + kk;
                Bs[kk][nn] = (k < AF && c < HH) ? W[k * HH + c] : 0.f;
            }
        }
        __syncthreads();
        #pragma unroll
        for (int kk = 0; kk < 16; kk++) {
            float4 a4 = *(const float4*)&As[kk][ty * 4];
            float4 b4 = *(const float4*)&Bs[kk][tx * 4];
            float a[4] = {a4.x, a4.y, a4.z, a4.w};
            float b[4] = {b4.x, b4.y, b4.z, b4.w};
            #pragma unroll
            for (int i = 0; i < 4; i++)
                #pragma unroll
                for (int j = 0; j < 4; j++)
                    acc[i][j] += a[i] * b[j];
        }
    }
    #pragma unroll
    for (int i = 0; i < 4; i++) {
        int r = row0 + ty * 4 + i;
        #pragma unroll
        for (int j = 0; j < 4; j++) {
            int c = col0 + tx * 4 + j;
            if (c < HH) {
                float v = acc[i][j];
                v = v > 0.f ? v : 0.f;
                g_input_atom[r * HH + c] = v;
                g_msg_atom[r * HH + c]   = v;
            }
        }
    }
}

// ---------------------------------------------------------------------------
// agg over input_bond with adjacency skip
// ---------------------------------------------------------------------------
__global__ void k_agg(const float* __restrict__ mb, const float* __restrict__ adj) {
    int gm = blockIdx.x;
    int g = gm >> 6, m = gm & 63;
    __shared__ float adjc[64];
    int tid = threadIdx.x;
    if (tid < 64) adjc[tid] = adj[(size_t)(g * 64 + tid) * 64 + m];
    __syncthreads();
    int h = tid;
    if (h >= HH) return;
    const float* base = mb + ((size_t)(g * 64) * 64 + m) * HH + h;
    float s = 0.f, mx = 0.f;
    for (int n = 0; n < 64; n++) {
        if (adjc[n] != 0.f) {
            float v = base[(size_t)n * 64 * HH];
            s += v;
            mx = fmaxf(mx, v);
        }
    }
    float a = s * (1.f / (1.f + expf(-mx)));
    g_msg_atom[gm * HH + h] += a;
}

// ---------------------------------------------------------------------------
__global__ void k_resonance2(const float* __restrict__ adj) {
    int g = blockIdx.x;
    __shared__ float mt[64][101];
    __shared__ float rr[64][65];
    int tid = threadIdx.x;
    int tx = tid & 15, ty = tid >> 4;
    float acc[4][4] = {};
    for (int c = 0; c < 3; ++c) {
        __syncthreads();
        for (int l = tid; l < 6400; l += 256) {
            int r = l / 100, k = l - r * 100;
            mt[r][k] = g_msg_atom[((size_t)(g * 64 + r)) * 300 + c * 100 + k];
        }
        __syncthreads();
        for (int kk = 0; kk < 100; ++kk) {
            float a[4], b[4];
            #pragma unroll
            for (int i = 0; i < 4; i++) a[i] = mt[ty * 4 + i][kk];
            #pragma unroll
            for (int j = 0; j < 4; j++) b[j] = mt[tx * 4 + j][kk];
            #pragma unroll
            for (int i = 0; i < 4; i++)
                #pragma unroll
                for (int j = 0; j < 4; j++)
                    acc[i][j] += a[i] * b[j];
        }
    }
    #pragma unroll
    for (int i = 0; i < 4; i++)
        #pragma unroll
        for (int j = 0; j < 4; j++)
            rr[ty * 4 + i][tx * 4 + j] = acc[i][j];
    __syncthreads();
    if (tid < 64) {
        int m = tid;
        float mxv = -INFINITY;
        for (int n = 0; n < 64; n++) {
            float v = rr[n][m] * adj[((size_t)(g * 64 + n)) * 64 + m];
            rr[n][m] = v;
            mxv = fmaxf(mxv, v);
        }
        float sum = 0.f;
        for (int n = 0; n < 64; n++) {
            float e = expf(rr[n][m] - mxv);
            rr[n][m] = e;
            sum += e;
        }
        float inv = 1.f / sum;
        for (int n = 0; n < 64; n++)
            g_sm[(size_t)(g * 64 + n) * 64 + m] = rr[n][m] * inv;
    }
}

// ---------------------------------------------------------------------------
__global__ void k_output(const float* __restrict__ W, const float* __restrict__ bias,
                         float* __restrict__ out) {
    const int row0 = blockIdx.y * 64;
    const int col0 = blockIdx.x * 64;
    __shared__ float As[16][68];
    __shared__ float Bs[16][68];
    const int tid = threadIdx.x;
    const int tx = tid & 15, ty = tid >> 4;
    float acc[4][4] = {};
    for (int k0 = 0; k0 < 900; k0 += 16) {
        __syncthreads();
        {
            int kk = tid & 15;
            int k  = k0 + kk;
            #pragma unroll
            for (int qq = 0; qq < 4; qq++) {
                int r = (tid >> 4) + qq * 16;
                int row = row0 + r;
                float v = 0.f;
                if (k < 900) {
                    if (k < 300)       v = g_agg[row * HH + k];
                    else if (k < 600)  v = g_msg_atom[row * HH + (k - 300)];
                    else               v = g_input_atom[row * HH + (k - 600)];
                }
                As[kk][r] = v;
            }
        }
        {
            int nn = tid & 63;
            int c  = col0 + nn;
            #pragma unroll
            for (int qq = 0; qq < 4; qq++) {
                int kk = (tid >> 6) + qq * 4;
                int k  = k0 + kk;
                Bs[kk][nn] = (k < 900 && c < HH) ? W[k * HH + c] : 0.f;
            }
        }
        __syncthreads();
        #pragma unroll
        for (int kk = 0; kk < 16; kk++) {
            float4 a4 = *(const float4*)&As[kk][ty * 4];
            float4 b4 = *(const float4*)&Bs[kk][tx * 4];
            float a[4] = {a4.x, a4.y, a4.z, a4.w};
            float b[4] = {b4.x, b4.y, b4.z, b4.w};
            #pragma unroll
            for (int i = 0; i < 4; i++)
                #pragma unroll
                for (int j = 0; j < 4; j++)
                    acc[i][j] += a[i] * b[j];
        }
    }
    #pragma unroll
    for (int i = 0; i < 4; i++) {
        int r = row0 + ty * 4 + i;
        #pragma unroll
        for (int j = 0; j < 4; j++) {
            int c = col0 + tx * 4 + j;
            if (c < HH) {
                float v = acc[i][j] + bias[c];
                out[r * HH + c] = v > 0.f ? v : 0.f;
            }
        }
    }
}

// ---------------------------------------------------------------------------
extern "C" void kernel_launch(void* const* d_in, const int* in_sizes, int n_in,
                              void* d_out, int out_size) {
    const float* f_atoms  = (const float*)d_in[0];
    const float* f_bonds  = (const float*)d_in[1];
    const float* adj      = (const float*)d_in[2];
    const float* W_i_atom = (const float*)d_in[3];
    const float* W_i_bond = (const float*)d_in[4];
    const float* W_h0     = (const float*)d_in[5];
    const float* W_h1     = (const float*)d_in[6];
    const float* W_o      = (const float*)d_in[7];
    const float* b_o      = (const float*)d_in[8];
    float* out = (float*)d_out;

    float *p_inbond = 0, *p_mbB = 0, *p_msg = 0, *p_maW = 0;
    __nv_bfloat16 *p0h = 0, *p0l = 0, *p1h = 0, *p1l = 0;
    __nv_bfloat16 *wt0h = 0, *wt0l = 0, *wt1h = 0, *wt1l = 0;
    cudaGetSymbolAddress((void**)&p_inbond, g_input_bond);
    cudaGetSymbolAddress((void**)&p_mbB, g_mbB);
    cudaGetSymbolAddress((void**)&p_msg, g_msg_atom);
    cudaGetSymbolAddress((void**)&p_maW, g_maW);
    cudaGetSymbolAddress((void**)&p0h, g_P0h);
    cudaGetSymbolAddress((void**)&p0l, g_P0l);
    cudaGetSymbolAddress((void**)&p1h, g_P1h);
    cudaGetSymbolAddress((void**)&p1l, g_P1l);
    cudaGetSymbolAddress((void**)&wt0h, g_Wt0h);
    cudaGetSymbolAddress((void**)&wt0l, g_Wt0l);
    cudaGetSymbolAddress((void**)&wt1h, g_Wt1h);
    cudaGetSymbolAddress((void**)&wt1l, g_Wt1l);

    float* mb_final = (out_size >= AR * HH + BR * HH) ? (out + AR * HH) : p_mbB;

    const int SMEM_MMA = 66560;
    cudaFuncSetAttribute(k_bondstep_mma<1, 1, 0>,
                         cudaFuncAttributeMaxDynamicSharedMemorySize, SMEM_MMA);
    cudaFuncSetAttribute(k_bondstep_mma<0, 0, 1>,
                         cudaFuncAttributeMaxDynamicSharedMemorySize, SMEM_MMA);

    // sparsity compaction (adj binary, ~30% dense)
    k_reset<<<1, 32>>>();
    k_compact<<<(BR + 255) / 256, 256>>>(adj);

    k_input_atom<<<dim3(5, 32), 256>>>(f_atoms, W_i_atom);
    k_convW<<<HH, KP>>>(W_h0, wt0h, wt0l);
    k_convW<<<HH, KP>>>(W_h1, wt1h, wt1l);
    // input_bond over nonzero rows only (fp32 + bf16 planes P0)
    k_inbond_idx<<<dim3(5, BR / 128), 128>>>(f_bonds, W_i_bond, p_inbond, p0h, p0l);

    // ---- depth step 0 (prev = input_bond) ----
    k_agg<<<2048, 320>>>(p_inbond, adj);
    k_resonance2<<<32, 256>>>(adj);
    k_gemm_f2<HH><<<dim3(5, AR / 128), 128>>>(p_msg, W_h0, p_maW, HH);
    k_bondstep_mma<1, 1, 0><<<dim3(5, BR / 128), 256, SMEM_MMA>>>(
        p0h, p0l, wt0h, wt0l, p_inbond, p_maW, adj, mb_final, p1h, p1l);

    // ---- depth step 1 (prev = mbA planes) ----
    k_resonance2<<<32, 256>>>(adj);
    k_gemm_f2<HH><<<dim3(5, AR / 128), 128>>>(p_msg, W_h1, p_maW, HH);
    k_bondstep_mma<0, 0, 1><<<dim3(5, BR / 128), 256, SMEM_MMA>>>(
        p1h, p1l, wt1h, wt1l, p_inbond, p_maW, adj, mb_final, nullptr, nullptr);

    // ---- readout ----
    k_output<<<dim3(5, 32), 256>>>(W_o, b_o, out);
}